// round 9
// baseline (speedup 1.0000x reference)
#include <cuda_runtime.h>
#include <math.h>
#include <stdint.h>

#define Bz   8
#define Cc   512
#define Nn   4096
#define Mm   64
#define EPSc 1e-6f

// ---------------- device scratch ----------------
__device__ float g_Qf[Bz*Mm*Nn];   // softplus(Q)  [b][m][n]
__device__ float g_Kf[Bz*Mm*Nn];   // softplus(K)  [b][m][n]
__device__ float g_S [Bz*Mm*Cc];   // Kf . x^T     [b][m][c']
__device__ float g_KV[Bz*Mm*Cc];   // gated KV     [b][m][c]
__device__ float g_Ks2[Bz*Mm];     // sum_n Kf
__device__ float g_gmax[Bz*Cc];
__device__ float g_gsum[Bz*Cc];

// ---------------- helpers ----------------
__device__ __forceinline__ uint32_t f2tf32(float f) {
    uint32_t r;
    asm("cvt.rna.tf32.f32 %0, %1;" : "=r"(r) : "f"(f));
    return r;
}
__device__ __forceinline__ void mma_tf32(float* d, const uint32_t* a, const uint32_t* b) {
    asm volatile(
        "mma.sync.aligned.m16n8k8.row.col.f32.tf32.tf32.f32 "
        "{%0,%1,%2,%3}, {%4,%5,%6,%7}, {%8,%9}, {%0,%1,%2,%3};"
        : "+f"(d[0]), "+f"(d[1]), "+f"(d[2]), "+f"(d[3])
        : "r"(a[0]), "r"(a[1]), "r"(a[2]), "r"(a[3]), "r"(b[0]), "r"(b[1]));
}
__device__ __forceinline__ void atomicMaxF(float* addr, float v) {
    if (v >= 0.f) atomicMax((int*)addr, __float_as_int(v));
    else          atomicMin((unsigned int*)addr, __float_as_uint(v));
}
__device__ __forceinline__ float softplus_f(float v) {
    return fmaxf(v, 0.f) + __logf(1.f + __expf(-fabsf(v)));
}

// ---------------- kernel: zero scratch ----------------
__global__ void zero_kernel() {
    int i = blockIdx.x * 256 + threadIdx.x;
    if (i < Bz*Mm*Cc) g_S[i] = 0.f;
    if (i < Bz*Mm) g_Ks2[i] = 0.f;
    if (i < Bz*Cc) { g_gmax[i] = -INFINITY; g_gsum[i] = 0.f; }
}

// ---------------- kernel: Q,K projection GEMM (tf32 mma) ----------------
// D[r][n] = sum_c W[r][c] * x[b][c][n], r in [0,128): rows 0..63 wq, 64..127 wk
__global__ __launch_bounds__(256, 2) void qk_mma_kernel(
    const float* __restrict__ x,
    const float* __restrict__ wq, const float* __restrict__ bq,
    const float* __restrict__ wk, const float* __restrict__ bk)
{
    __shared__ uint32_t As[128][36];   // [r][k]
    __shared__ uint32_t Xs[32][132];   // [k][n] natural

    const int tid = threadIdx.x;
    const int wid = tid >> 5;
    const int lid = tid & 31;
    const int g4  = lid >> 2;
    const int l4  = lid & 3;
    const int wm  = wid >> 1;          // 0..3 over r
    const int wn  = wid & 1;           // 0..1 over n

    const int n0 = blockIdx.x * 128;
    const int b  = blockIdx.y;

    const float* xb = x + (size_t)b * Cc * Nn;

    float acc[2][8][4];
    #pragma unroll
    for (int mi = 0; mi < 2; mi++)
        #pragma unroll
        for (int ni = 0; ni < 8; ni++)
            #pragma unroll
            for (int q = 0; q < 4; q++) acc[mi][ni][q] = 0.f;

    const int lrow = tid >> 3;          // 0..31
    const int lf   = (tid & 7) * 4;

    float4 pb[4];
    #pragma unroll
    for (int p = 0; p < 4; p++) {
        int idx = tid + p * 256;
        pb[p] = *(const float4*)(xb + (size_t)(idx >> 5) * Nn + n0 + (idx & 31) * 4);
    }

    for (int kc = 0; kc < Cc; kc += 32) {
        if (kc) __syncthreads();
        #pragma unroll
        for (int p = 0; p < 4; p++) {
            int row = lrow + p * 32;
            const float* wsrc = (row < Mm) ? (wq + (size_t)row * Cc)
                                           : (wk + (size_t)(row - Mm) * Cc);
            float4 va = *(const float4*)(wsrc + kc + lf);
            uint4 ua = { f2tf32(va.x), f2tf32(va.y), f2tf32(va.z), f2tf32(va.w) };
            *(uint4*)&As[row][lf] = ua;
        }
        #pragma unroll
        for (int p = 0; p < 4; p++) {
            int idx = tid + p * 256;
            uint4 ub = { f2tf32(pb[p].x), f2tf32(pb[p].y), f2tf32(pb[p].z), f2tf32(pb[p].w) };
            *(uint4*)&Xs[idx >> 5][(idx & 31) * 4] = ub;
        }
        __syncthreads();
        if (kc + 32 < Cc) {
            #pragma unroll
            for (int p = 0; p < 4; p++) {
                int idx = tid + p * 256;
                pb[p] = *(const float4*)(xb + (size_t)(kc + 32 + (idx >> 5)) * Nn + n0 + (idx & 31) * 4);
            }
        }
        #pragma unroll
        for (int k8 = 0; k8 < 4; k8++) {
            const int kb = k8 * 8;
            uint32_t afr[2][4];
            #pragma unroll
            for (int mi = 0; mi < 2; mi++) {
                int mr = wm * 32 + mi * 16;
                afr[mi][0] = As[mr + g4    ][kb + l4];
                afr[mi][1] = As[mr + g4 + 8][kb + l4];
                afr[mi][2] = As[mr + g4    ][kb + l4 + 4];
                afr[mi][3] = As[mr + g4 + 8][kb + l4 + 4];
            }
            uint32_t bfr[8][2];
            #pragma unroll
            for (int ni = 0; ni < 8; ni++) {
                int nr = wn * 64 + ni * 8 + g4;
                bfr[ni][0] = Xs[kb + l4    ][nr];
                bfr[ni][1] = Xs[kb + l4 + 4][nr];
            }
            #pragma unroll
            for (int mi = 0; mi < 2; mi++)
                #pragma unroll
                for (int ni = 0; ni < 8; ni++)
                    mma_tf32(acc[mi][ni], afr[mi], bfr[ni]);
        }
    }

    // epilogue: bias + softplus; ksum for K rows
    #pragma unroll
    for (int mi = 0; mi < 2; mi++) {
        #pragma unroll
        for (int h = 0; h < 2; h++) {
            const int r = wm * 32 + mi * 16 + h * 8 + g4;
            float bias; float* dst; bool isK;
            if (r < Mm) { bias = bq[r];      dst = g_Qf + (size_t)(b*Mm + r) * Nn;      isK = false; }
            else        { bias = bk[r - Mm]; dst = g_Kf + (size_t)(b*Mm + r - Mm) * Nn; isK = true;  }
            float ks = 0.f;
            #pragma unroll
            for (int ni = 0; ni < 8; ni++) {
                float v0 = softplus_f(acc[mi][ni][h*2 + 0] + bias);
                float v1 = softplus_f(acc[mi][ni][h*2 + 1] + bias);
                if (isK) ks += v0 + v1;
                float2 w2 = { v0, v1 };
                *(float2*)(dst + n0 + wn * 64 + ni * 8 + l4 * 2) = w2;
            }
            if (isK) {
                ks += __shfl_xor_sync(0xffffffffu, ks, 1);
                ks += __shfl_xor_sync(0xffffffffu, ks, 2);
                if (l4 == 0) atomicAdd(&g_Ks2[b*Mm + (r - Mm)], ks);
            }
        }
    }
}

// ---------------- kernel: S = Kf . x^T (split-k over n) + fused gate partials ----------------
__global__ __launch_bounds__(256, 2) void s_mma_kernel(const float* __restrict__ x) {
    __shared__ uint32_t As[64][36];    // [m][k]
    __shared__ uint32_t Bs[128][36];   // [c'][k]

    const int tid = threadIdx.x;
    const int wid = tid >> 5;
    const int lid = tid & 31;
    const int g4  = lid >> 2;
    const int l4  = lid & 3;
    const int wm  = wid >> 2;          // 0..1
    const int wn  = wid & 3;           // 0..3

    const int b     = blockIdx.z;
    const int c0    = blockIdx.y * 128;
    const int nbase = blockIdx.x * 512;

    const float* kf = g_Kf + (size_t)b * Mm * Nn;
    const float* xp = x + ((size_t)(b*Cc + c0)) * Nn;

    float acc[2][4][4];
    #pragma unroll
    for (int mi = 0; mi < 2; mi++)
        #pragma unroll
        for (int ni = 0; ni < 4; ni++)
            #pragma unroll
            for (int q = 0; q < 4; q++) acc[mi][ni][q] = 0.f;

    float gmx[4] = {-INFINITY, -INFINITY, -INFINITY, -INFINITY};
    float gsm[4] = {0.f, 0.f, 0.f, 0.f};

    const int lrow = tid >> 3;
    const int lf   = (tid & 7) * 4;

    float4 pa[2], pb[4];
    #pragma unroll
    for (int p = 0; p < 2; p++)
        pa[p] = *(const float4*)(kf + (size_t)(lrow + p*32) * Nn + nbase + lf);
    #pragma unroll
    for (int p = 0; p < 4; p++)
        pb[p] = *(const float4*)(xp + (size_t)(lrow + p*32) * Nn + nbase + lf);

    for (int nc = 0; nc < 512; nc += 32) {
        if (nc) __syncthreads();
        #pragma unroll
        for (int p = 0; p < 2; p++) {
            uint4 ua = { f2tf32(pa[p].x), f2tf32(pa[p].y), f2tf32(pa[p].z), f2tf32(pa[p].w) };
            *(uint4*)&As[lrow + p*32][lf] = ua;
        }
        #pragma unroll
        for (int p = 0; p < 4; p++) {
            float4 v = pb[p];
            gmx[p] = fmaxf(gmx[p], fmaxf(fmaxf(v.x, v.y), fmaxf(v.z, v.w)));
            gsm[p] += (v.x + v.y) + (v.z + v.w);
            uint4 ub = { f2tf32(v.x), f2tf32(v.y), f2tf32(v.z), f2tf32(v.w) };
            *(uint4*)&Bs[lrow + p*32][lf] = ub;
        }
        __syncthreads();
        if (nc + 32 < 512) {
            int n = nbase + nc + 32;
            #pragma unroll
            for (int p = 0; p < 2; p++)
                pa[p] = *(const float4*)(kf + (size_t)(lrow + p*32) * Nn + n + lf);
            #pragma unroll
            for (int p = 0; p < 4; p++)
                pb[p] = *(const float4*)(xp + (size_t)(lrow + p*32) * Nn + n + lf);
        }
        #pragma unroll
        for (int k8 = 0; k8 < 4; k8++) {
            const int kb = k8 * 8;
            uint32_t afr[2][4];
            #pragma unroll
            for (int mi = 0; mi < 2; mi++) {
                int mr = wm * 32 + mi * 16;
                afr[mi][0] = As[mr + g4    ][kb + l4];
                afr[mi][1] = As[mr + g4 + 8][kb + l4];
                afr[mi][2] = As[mr + g4    ][kb + l4 + 4];
                afr[mi][3] = As[mr + g4 + 8][kb + l4 + 4];
            }
            uint32_t bfr[4][2];
            #pragma unroll
            for (int ni = 0; ni < 4; ni++) {
                int nr = wn * 32 + ni * 8 + g4;
                bfr[ni][0] = Bs[nr][kb + l4];
                bfr[ni][1] = Bs[nr][kb + l4 + 4];
            }
            #pragma unroll
            for (int mi = 0; mi < 2; mi++)
                #pragma unroll
                for (int ni = 0; ni < 4; ni++)
                    mma_tf32(acc[mi][ni], afr[mi], bfr[ni]);
        }
    }

    // gate partials
    #pragma unroll
    for (int p = 0; p < 4; p++) {
        float mx = gmx[p], sm = gsm[p];
        #pragma unroll
        for (int o = 1; o < 8; o <<= 1) {
            mx = fmaxf(mx, __shfl_xor_sync(0xffffffffu, mx, o));
            sm += __shfl_xor_sync(0xffffffffu, sm, o);
        }
        if ((lid & 7) == 0) {
            int c = c0 + lrow + p * 32;
            atomicMaxF(&g_gmax[b*Cc + c], mx);
            atomicAdd(&g_gsum[b*Cc + c], sm);
        }
    }

    // accumulate S
    #pragma unroll
    for (int mi = 0; mi < 2; mi++) {
        #pragma unroll
        for (int h = 0; h < 2; h++) {
            const int m = wm * 32 + mi * 16 + h * 8 + g4;
            float* srow = g_S + (size_t)(b*Mm + m) * Cc + c0;
            #pragma unroll
            for (int ni = 0; ni < 4; ni++) {
                int c = wn * 32 + ni * 8 + l4 * 2;
                atomicAdd(srow + c,     acc[mi][ni][h*2 + 0]);
                atomicAdd(srow + c + 1, acc[mi][ni][h*2 + 1]);
            }
        }
    }
}

// ---------------- kernel: KV = gate * (S . Wv^T + Ks2 (x) bv), gate inlined ----------------
__global__ __launch_bounds__(256) void kv2_kernel(const float* __restrict__ wv,
                                                  const float* __restrict__ bv) {
    __shared__ uint32_t As[64][36];    // [m][k=c']
    __shared__ uint32_t Bs[64][36];    // [c][k=c']

    const int tid = threadIdx.x;
    const int wid = tid >> 5;
    const int lid = tid & 31;
    const int g4  = lid >> 2;
    const int l4  = lid & 3;
    const int wm  = wid >> 2;          // 0..1
    const int wn  = wid & 3;           // 0..3

    const int c0 = blockIdx.x * 64;
    const int b  = blockIdx.y;

    const float* sp  = g_S + (size_t)b * Mm * Cc;
    const float* wvp = wv + (size_t)c0 * Cc;

    float acc[2][2][4];
    #pragma unroll
    for (int mi = 0; mi < 2; mi++)
        #pragma unroll
        for (int ni = 0; ni < 2; ni++)
            #pragma unroll
            for (int q = 0; q < 4; q++) acc[mi][ni][q] = 0.f;

    for (int kc = 0; kc < Cc; kc += 32) {
        if (kc) __syncthreads();
        #pragma unroll
        for (int p = 0; p < 2; p++) {
            int idx = tid + p * 256;
            int row = idx >> 3;
            int lf  = (idx & 7) * 4;
            float4 va = *(const float4*)(sp + (size_t)row * Cc + kc + lf);
            uint4 ua = { f2tf32(va.x), f2tf32(va.y), f2tf32(va.z), f2tf32(va.w) };
            *(uint4*)&As[row][lf] = ua;
            float4 vb = *(const float4*)(wvp + (size_t)row * Cc + kc + lf);
            uint4 ub = { f2tf32(vb.x), f2tf32(vb.y), f2tf32(vb.z), f2tf32(vb.w) };
            *(uint4*)&Bs[row][lf] = ub;
        }
        __syncthreads();
        #pragma unroll
        for (int k8 = 0; k8 < 4; k8++) {
            const int kb = k8 * 8;
            uint32_t afr[2][4];
            #pragma unroll
            for (int mi = 0; mi < 2; mi++) {
                int mr = wm * 32 + mi * 16;
                afr[mi][0] = As[mr + g4    ][kb + l4];
                afr[mi][1] = As[mr + g4 + 8][kb + l4];
                afr[mi][2] = As[mr + g4    ][kb + l4 + 4];
                afr[mi][3] = As[mr + g4 + 8][kb + l4 + 4];
            }
            uint32_t bfr[2][2];
            #pragma unroll
            for (int ni = 0; ni < 2; ni++) {
                int nr = wn * 16 + ni * 8 + g4;
                bfr[ni][0] = Bs[nr][kb + l4];
                bfr[ni][1] = Bs[nr][kb + l4 + 4];
            }
            #pragma unroll
            for (int mi = 0; mi < 2; mi++)
                #pragma unroll
                for (int ni = 0; ni < 2; ni++)
                    mma_tf32(acc[mi][ni], afr[mi], bfr[ni]);
        }
    }

    #pragma unroll
    for (int mi = 0; mi < 2; mi++) {
        #pragma unroll
        for (int h = 0; h < 2; h++) {
            const int m = wm * 32 + mi * 16 + h * 8 + g4;
            const float ksm = g_Ks2[b*Mm + m];
            float* kvrow = g_KV + (size_t)(b*Mm + m) * Cc;
            #pragma unroll
            for (int ni = 0; ni < 2; ni++) {
                int c = c0 + wn * 16 + ni * 8 + l4 * 2;
                float gt0 = g_gmax[b*Cc + c]     + g_gsum[b*Cc + c]     * (1.f / Nn);
                float gt1 = g_gmax[b*Cc + c + 1] + g_gsum[b*Cc + c + 1] * (1.f / Nn);
                float v0 = gt0 * (acc[mi][ni][h*2 + 0] + ksm * bv[c]);
                float v1 = gt1 * (acc[mi][ni][h*2 + 1] + ksm * bv[c + 1]);
                float2 w2 = { v0, v1 };
                *(float2*)(kvrow + c) = w2;
            }
        }
    }
}

// ---------------- kernel: out = x + gamma * norm * (KV^T @ Qf), 512 thr, c-tile 256 ----------------
#define OSTR_N 136
#define OSTR_C 264
#define OUT_SMEM ((64*OSTR_N + 64*OSTR_C + 64 + 128) * 4)
__global__ __launch_bounds__(512) void out_mma_kernel(const float* __restrict__ x,
                                                      const float* __restrict__ gamma,
                                                      float* __restrict__ out) {
    extern __shared__ uint32_t osm[];
    uint32_t* Qs  = osm;                           // [64][136]
    uint32_t* KVs = osm + 64 * OSTR_N;             // [64][264]
    float* ks_s   = (float*)(osm + 64*OSTR_N + 64*OSTR_C);  // [64]
    float* nrm_s  = ks_s + 64;                               // [128]

    const int tid = threadIdx.x;
    const int wid = tid >> 5;
    const int lid = tid & 31;
    const int g4  = lid >> 2;
    const int l4  = lid & 3;
    const int wm  = wid >> 2;          // 0..3  (c, 64 each)
    const int wn  = wid & 3;           // 0..3  (n, 32 each)

    const int n0 = blockIdx.x * 128;
    const int c0 = blockIdx.y * 256;
    const int b  = blockIdx.z;

    const float* qb  = g_Qf + (size_t)b * Mm * Nn;
    const float* kvb = g_KV + (size_t)b * Mm * Cc;

    #pragma unroll
    for (int p = 0; p < 4; p++) {
        int idx = tid + p * 512;
        int row = idx >> 5;
        int c4  = (idx & 31) * 4;
        float4 q = *(const float4*)(qb + (size_t)row * Nn + n0 + c4);
        uint4 uq = { f2tf32(q.x), f2tf32(q.y), f2tf32(q.z), f2tf32(q.w) };
        *(uint4*)&Qs[row * OSTR_N + c4] = uq;
    }
    #pragma unroll
    for (int p = 0; p < 8; p++) {
        int idx = tid + p * 512;
        int row = idx >> 6;
        int c4  = (idx & 63) * 4;
        float4 kv = *(const float4*)(kvb + (size_t)row * Cc + c0 + c4);
        uint4 uk = { f2tf32(kv.x), f2tf32(kv.y), f2tf32(kv.z), f2tf32(kv.w) };
        *(uint4*)&KVs[row * OSTR_C + c4] = uk;
    }
    if (tid < 64) ks_s[tid] = g_Ks2[b*Mm + tid] + EPSc;
    __syncthreads();

    if (tid < 128) {
        float s = 0.f;
        #pragma unroll
        for (int m = 0; m < Mm; m++)
            s = fmaf(__uint_as_float(Qs[m * OSTR_N + tid]), ks_s[m], s);
        nrm_s[tid] = 1.f / s;
    }
    __syncthreads();

    float acc[4][4][4];
    #pragma unroll
    for (int mi = 0; mi < 4; mi++)
        #pragma unroll
        for (int ni = 0; ni < 4; ni++)
            #pragma unroll
            for (int q = 0; q < 4; q++) acc[mi][ni][q] = 0.f;

    #pragma unroll
    for (int k8 = 0; k8 < 8; k8++) {
        const int kb = k8 * 8;
        uint32_t afr[4][4];
        #pragma unroll
        for (int mi = 0; mi < 4; mi++) {
            int cr = wm * 64 + mi * 16;
            afr[mi][0] = KVs[(kb + l4    ) * OSTR_C + cr + g4];
            afr[mi][1] = KVs[(kb + l4    ) * OSTR_C + cr + g4 + 8];
            afr[mi][2] = KVs[(kb + l4 + 4) * OSTR_C + cr + g4];
            afr[mi][3] = KVs[(kb + l4 + 4) * OSTR_C + cr + g4 + 8];
        }
        uint32_t bfr[4][2];
        #pragma unroll
        for (int ni = 0; ni < 4; ni++) {
            int nr = wn * 32 + ni * 8 + g4;
            bfr[ni][0] = Qs[(kb + l4    ) * OSTR_N + nr];
            bfr[ni][1] = Qs[(kb + l4 + 4) * OSTR_N + nr];
        }
        #pragma unroll
        for (int mi = 0; mi < 4; mi++)
            #pragma unroll
            for (int ni = 0; ni < 4; ni++)
                mma_tf32(acc[mi][ni], afr[mi], bfr[ni]);
    }

    const float g = gamma[0];
    float2 nrm[4];
    #pragma unroll
    for (int ni = 0; ni < 4; ni++)
        nrm[ni] = *(float2*)&nrm_s[wn*32 + ni*8 + l4*2];

    #pragma unroll
    for (int mi = 0; mi < 4; mi++) {
        #pragma unroll
        for (int h = 0; h < 2; h++) {
            const int c = c0 + wm * 64 + mi * 16 + h * 8 + g4;
            const size_t off = ((size_t)(b * Cc + c)) * Nn + n0;
            #pragma unroll
            for (int ni = 0; ni < 4; ni++) {
                int ncol = wn * 32 + ni * 8 + l4 * 2;
                float2 xv = *(const float2*)(x + off + ncol);
                float2 r;
                r.x = xv.x + g * nrm[ni].x * acc[mi][ni][h*2 + 0];
                r.y = xv.y + g * nrm[ni].y * acc[mi][ni][h*2 + 1];
                *(float2*)(out + off + ncol) = r;
            }
        }
    }
}

// ---------------- launch (single stream, no host resource creation) ----------------
extern "C" void kernel_launch(void* const* d_in, const int* in_sizes, int n_in,
                              void* d_out, int out_size) {
    const float* x     = (const float*)d_in[0];
    const float* wq    = (const float*)d_in[1];
    const float* bq    = (const float*)d_in[2];
    const float* wk    = (const float*)d_in[3];
    const float* bk    = (const float*)d_in[4];
    const float* wv    = (const float*)d_in[5];
    const float* bv    = (const float*)d_in[6];
    const float* gamma = (const float*)d_in[7];
    float* out = (float*)d_out;

    cudaFuncSetAttribute(out_mma_kernel, cudaFuncAttributeMaxDynamicSharedMemorySize, OUT_SMEM);

    zero_kernel<<<(Bz*Mm*Cc + 255) / 256, 256>>>();
    qk_mma_kernel<<<dim3(Nn/128, Bz), 256>>>(x, wq, bq, wk, bk);
    s_mma_kernel<<<dim3(8, Cc/128, Bz), 256>>>(x);
    kv2_kernel<<<dim3(Cc/64, Bz), 256>>>(wv, bv);
    out_mma_kernel<<<dim3(Nn/128, Cc/256, Bz), 512, OUT_SMEM>>>(x, gamma, out);
}

// round 10
// speedup vs baseline: 1.0923x; 1.0923x over previous
#include <cuda_runtime.h>
#include <math.h>
#include <stdint.h>

#define Bz   8
#define Cc   512
#define Nn   4096
#define Mm   64
#define EPSc 1e-6f

// ---------------- device scratch ----------------
__device__ float g_Qf[Bz*Mm*Nn];   // softplus(Q)  [b][m][n]
__device__ float g_Kf[Bz*Mm*Nn];   // softplus(K)  [b][m][n]
__device__ float g_S [Bz*Mm*Cc];   // Kf . x^T     [b][m][c']
__device__ float g_KV[Bz*Mm*Cc];   // RAW S.Wv^T accumulator [b][m][c]
__device__ float g_Ks2[Bz*Mm];     // sum_n Kf
__device__ float g_gmax[Bz*Cc];
__device__ float g_gsum[Bz*Cc];

// ---------------- helpers ----------------
__device__ __forceinline__ uint32_t f2tf32(float f) {
    uint32_t r;
    asm("cvt.rna.tf32.f32 %0, %1;" : "=r"(r) : "f"(f));
    return r;
}
__device__ __forceinline__ void mma_tf32(float* d, const uint32_t* a, const uint32_t* b) {
    asm volatile(
        "mma.sync.aligned.m16n8k8.row.col.f32.tf32.tf32.f32 "
        "{%0,%1,%2,%3}, {%4,%5,%6,%7}, {%8,%9}, {%0,%1,%2,%3};"
        : "+f"(d[0]), "+f"(d[1]), "+f"(d[2]), "+f"(d[3])
        : "r"(a[0]), "r"(a[1]), "r"(a[2]), "r"(a[3]), "r"(b[0]), "r"(b[1]));
}
__device__ __forceinline__ void atomicMaxF(float* addr, float v) {
    if (v >= 0.f) atomicMax((int*)addr, __float_as_int(v));
    else          atomicMin((unsigned int*)addr, __float_as_uint(v));
}
__device__ __forceinline__ float softplus_f(float v) {
    return fmaxf(v, 0.f) + __logf(1.f + __expf(-fabsf(v)));
}

// ---------------- kernel: zero scratch ----------------
__global__ void zero_kernel() {
    int i = blockIdx.x * 256 + threadIdx.x;
    if (i < Bz*Mm*Cc) { g_S[i] = 0.f; g_KV[i] = 0.f; }
    if (i < Bz*Mm) g_Ks2[i] = 0.f;
    if (i < Bz*Cc) { g_gmax[i] = -INFINITY; g_gsum[i] = 0.f; }
}

// ---------------- kernel: Q,K projection GEMM (tf32 mma) ----------------
// D[r][n] = sum_c W[r][c] * x[b][c][n], r in [0,128): rows 0..63 wq, 64..127 wk
__global__ __launch_bounds__(256, 2) void qk_mma_kernel(
    const float* __restrict__ x,
    const float* __restrict__ wq, const float* __restrict__ bq,
    const float* __restrict__ wk, const float* __restrict__ bk)
{
    __shared__ uint32_t As[128][36];   // [r][k]
    __shared__ uint32_t Xs[32][132];   // [k][n] natural

    const int tid = threadIdx.x;
    const int wid = tid >> 5;
    const int lid = tid & 31;
    const int g4  = lid >> 2;
    const int l4  = lid & 3;
    const int wm  = wid >> 1;          // 0..3 over r
    const int wn  = wid & 1;           // 0..1 over n

    const int n0 = blockIdx.x * 128;
    const int b  = blockIdx.y;

    const float* xb = x + (size_t)b * Cc * Nn;

    float acc[2][8][4];
    #pragma unroll
    for (int mi = 0; mi < 2; mi++)
        #pragma unroll
        for (int ni = 0; ni < 8; ni++)
            #pragma unroll
            for (int q = 0; q < 4; q++) acc[mi][ni][q] = 0.f;

    const int lrow = tid >> 3;          // 0..31
    const int lf   = (tid & 7) * 4;

    float4 pb[4];
    #pragma unroll
    for (int p = 0; p < 4; p++) {
        int idx = tid + p * 256;
        pb[p] = *(const float4*)(xb + (size_t)(idx >> 5) * Nn + n0 + (idx & 31) * 4);
    }

    for (int kc = 0; kc < Cc; kc += 32) {
        if (kc) __syncthreads();
        #pragma unroll
        for (int p = 0; p < 4; p++) {
            int row = lrow + p * 32;
            const float* wsrc = (row < Mm) ? (wq + (size_t)row * Cc)
                                           : (wk + (size_t)(row - Mm) * Cc);
            float4 va = *(const float4*)(wsrc + kc + lf);
            uint4 ua = { f2tf32(va.x), f2tf32(va.y), f2tf32(va.z), f2tf32(va.w) };
            *(uint4*)&As[row][lf] = ua;
        }
        #pragma unroll
        for (int p = 0; p < 4; p++) {
            int idx = tid + p * 256;
            uint4 ub = { f2tf32(pb[p].x), f2tf32(pb[p].y), f2tf32(pb[p].z), f2tf32(pb[p].w) };
            *(uint4*)&Xs[idx >> 5][(idx & 31) * 4] = ub;
        }
        __syncthreads();
        if (kc + 32 < Cc) {
            #pragma unroll
            for (int p = 0; p < 4; p++) {
                int idx = tid + p * 256;
                pb[p] = *(const float4*)(xb + (size_t)(kc + 32 + (idx >> 5)) * Nn + n0 + (idx & 31) * 4);
            }
        }
        #pragma unroll
        for (int k8 = 0; k8 < 4; k8++) {
            const int kb = k8 * 8;
            uint32_t afr[2][4];
            #pragma unroll
            for (int mi = 0; mi < 2; mi++) {
                int mr = wm * 32 + mi * 16;
                afr[mi][0] = As[mr + g4    ][kb + l4];
                afr[mi][1] = As[mr + g4 + 8][kb + l4];
                afr[mi][2] = As[mr + g4    ][kb + l4 + 4];
                afr[mi][3] = As[mr + g4 + 8][kb + l4 + 4];
            }
            uint32_t bfr[8][2];
            #pragma unroll
            for (int ni = 0; ni < 8; ni++) {
                int nr = wn * 64 + ni * 8 + g4;
                bfr[ni][0] = Xs[kb + l4    ][nr];
                bfr[ni][1] = Xs[kb + l4 + 4][nr];
            }
            #pragma unroll
            for (int mi = 0; mi < 2; mi++)
                #pragma unroll
                for (int ni = 0; ni < 8; ni++)
                    mma_tf32(acc[mi][ni], afr[mi], bfr[ni]);
        }
    }

    // epilogue: bias + softplus; ksum for K rows
    #pragma unroll
    for (int mi = 0; mi < 2; mi++) {
        #pragma unroll
        for (int h = 0; h < 2; h++) {
            const int r = wm * 32 + mi * 16 + h * 8 + g4;
            float bias; float* dst; bool isK;
            if (r < Mm) { bias = bq[r];      dst = g_Qf + (size_t)(b*Mm + r) * Nn;      isK = false; }
            else        { bias = bk[r - Mm]; dst = g_Kf + (size_t)(b*Mm + r - Mm) * Nn; isK = true;  }
            float ks = 0.f;
            #pragma unroll
            for (int ni = 0; ni < 8; ni++) {
                float v0 = softplus_f(acc[mi][ni][h*2 + 0] + bias);
                float v1 = softplus_f(acc[mi][ni][h*2 + 1] + bias);
                if (isK) ks += v0 + v1;
                float2 w2 = { v0, v1 };
                *(float2*)(dst + n0 + wn * 64 + ni * 8 + l4 * 2) = w2;
            }
            if (isK) {
                ks += __shfl_xor_sync(0xffffffffu, ks, 1);
                ks += __shfl_xor_sync(0xffffffffu, ks, 2);
                if (l4 == 0) atomicAdd(&g_Ks2[b*Mm + (r - Mm)], ks);
            }
        }
    }
}

// ---------------- kernel: S = Kf . x^T (split-k over n) + fused gate partials ----------------
__global__ __launch_bounds__(256, 2) void s_mma_kernel(const float* __restrict__ x) {
    __shared__ uint32_t As[64][36];    // [m][k]
    __shared__ uint32_t Bs[128][36];   // [c'][k]

    const int tid = threadIdx.x;
    const int wid = tid >> 5;
    const int lid = tid & 31;
    const int g4  = lid >> 2;
    const int l4  = lid & 3;
    const int wm  = wid >> 2;          // 0..1
    const int wn  = wid & 3;           // 0..3

    const int b     = blockIdx.z;
    const int c0    = blockIdx.y * 128;
    const int nbase = blockIdx.x * 512;

    const float* kf = g_Kf + (size_t)b * Mm * Nn;
    const float* xp = x + ((size_t)(b*Cc + c0)) * Nn;

    float acc[2][4][4];
    #pragma unroll
    for (int mi = 0; mi < 2; mi++)
        #pragma unroll
        for (int ni = 0; ni < 4; ni++)
            #pragma unroll
            for (int q = 0; q < 4; q++) acc[mi][ni][q] = 0.f;

    float gmx[4] = {-INFINITY, -INFINITY, -INFINITY, -INFINITY};
    float gsm[4] = {0.f, 0.f, 0.f, 0.f};

    const int lrow = tid >> 3;
    const int lf   = (tid & 7) * 4;

    float4 pa[2], pb[4];
    #pragma unroll
    for (int p = 0; p < 2; p++)
        pa[p] = *(const float4*)(kf + (size_t)(lrow + p*32) * Nn + nbase + lf);
    #pragma unroll
    for (int p = 0; p < 4; p++)
        pb[p] = *(const float4*)(xp + (size_t)(lrow + p*32) * Nn + nbase + lf);

    for (int nc = 0; nc < 512; nc += 32) {
        if (nc) __syncthreads();
        #pragma unroll
        for (int p = 0; p < 2; p++) {
            uint4 ua = { f2tf32(pa[p].x), f2tf32(pa[p].y), f2tf32(pa[p].z), f2tf32(pa[p].w) };
            *(uint4*)&As[lrow + p*32][lf] = ua;
        }
        #pragma unroll
        for (int p = 0; p < 4; p++) {
            float4 v = pb[p];
            gmx[p] = fmaxf(gmx[p], fmaxf(fmaxf(v.x, v.y), fmaxf(v.z, v.w)));
            gsm[p] += (v.x + v.y) + (v.z + v.w);
            uint4 ub = { f2tf32(v.x), f2tf32(v.y), f2tf32(v.z), f2tf32(v.w) };
            *(uint4*)&Bs[lrow + p*32][lf] = ub;
        }
        __syncthreads();
        if (nc + 32 < 512) {
            int n = nbase + nc + 32;
            #pragma unroll
            for (int p = 0; p < 2; p++)
                pa[p] = *(const float4*)(kf + (size_t)(lrow + p*32) * Nn + n + lf);
            #pragma unroll
            for (int p = 0; p < 4; p++)
                pb[p] = *(const float4*)(xp + (size_t)(lrow + p*32) * Nn + n + lf);
        }
        #pragma unroll
        for (int k8 = 0; k8 < 4; k8++) {
            const int kb = k8 * 8;
            uint32_t afr[2][4];
            #pragma unroll
            for (int mi = 0; mi < 2; mi++) {
                int mr = wm * 32 + mi * 16;
                afr[mi][0] = As[mr + g4    ][kb + l4];
                afr[mi][1] = As[mr + g4 + 8][kb + l4];
                afr[mi][2] = As[mr + g4    ][kb + l4 + 4];
                afr[mi][3] = As[mr + g4 + 8][kb + l4 + 4];
            }
            uint32_t bfr[4][2];
            #pragma unroll
            for (int ni = 0; ni < 4; ni++) {
                int nr = wn * 32 + ni * 8 + g4;
                bfr[ni][0] = Bs[nr][kb + l4];
                bfr[ni][1] = Bs[nr][kb + l4 + 4];
            }
            #pragma unroll
            for (int mi = 0; mi < 2; mi++)
                #pragma unroll
                for (int ni = 0; ni < 4; ni++)
                    mma_tf32(acc[mi][ni], afr[mi], bfr[ni]);
        }
    }

    // gate partials
    #pragma unroll
    for (int p = 0; p < 4; p++) {
        float mx = gmx[p], sm = gsm[p];
        #pragma unroll
        for (int o = 1; o < 8; o <<= 1) {
            mx = fmaxf(mx, __shfl_xor_sync(0xffffffffu, mx, o));
            sm += __shfl_xor_sync(0xffffffffu, sm, o);
        }
        if ((lid & 7) == 0) {
            int c = c0 + lrow + p * 32;
            atomicMaxF(&g_gmax[b*Cc + c], mx);
            atomicAdd(&g_gsum[b*Cc + c], sm);
        }
    }

    // accumulate S
    #pragma unroll
    for (int mi = 0; mi < 2; mi++) {
        #pragma unroll
        for (int h = 0; h < 2; h++) {
            const int m = wm * 32 + mi * 16 + h * 8 + g4;
            float* srow = g_S + (size_t)(b*Mm + m) * Cc + c0;
            #pragma unroll
            for (int ni = 0; ni < 4; ni++) {
                int c = wn * 32 + ni * 8 + l4 * 2;
                atomicAdd(srow + c,     acc[mi][ni][h*2 + 0]);
                atomicAdd(srow + c + 1, acc[mi][ni][h*2 + 1]);
            }
        }
    }
}

// ---------------- kernel: KVraw += S . Wv^T  (split-k x2, prefetched) ----------------
__global__ __launch_bounds__(256, 2) void kv2_kernel(const float* __restrict__ wv) {
    __shared__ uint32_t As[64][36];    // [m][k]
    __shared__ uint32_t Bs[64][36];    // [c][k]

    const int tid = threadIdx.x;
    const int wid = tid >> 5;
    const int lid = tid & 31;
    const int g4  = lid >> 2;
    const int l4  = lid & 3;
    const int wm  = wid >> 2;          // 0..1
    const int wn  = wid & 3;           // 0..3

    const int c0 = blockIdx.x * 64;
    const int kh = blockIdx.y * 256;   // k-half base
    const int b  = blockIdx.z;

    const float* sp  = g_S + (size_t)b * Mm * Cc + kh;
    const float* wvp = wv + (size_t)c0 * Cc + kh;

    float acc[2][2][4];
    #pragma unroll
    for (int mi = 0; mi < 2; mi++)
        #pragma unroll
        for (int ni = 0; ni < 2; ni++)
            #pragma unroll
            for (int q = 0; q < 4; q++) acc[mi][ni][q] = 0.f;

    const int lrow = tid >> 3;          // 0..31
    const int lf   = (tid & 7) * 4;

    float4 pa[2], pb[2];
    #pragma unroll
    for (int p = 0; p < 2; p++) {
        pa[p] = *(const float4*)(sp  + (size_t)(lrow + p*32) * Cc + lf);
        pb[p] = *(const float4*)(wvp + (size_t)(lrow + p*32) * Cc + lf);
    }

    for (int kc = 0; kc < 256; kc += 32) {
        if (kc) __syncthreads();
        #pragma unroll
        for (int p = 0; p < 2; p++) {
            int row = lrow + p * 32;
            uint4 ua = { f2tf32(pa[p].x), f2tf32(pa[p].y), f2tf32(pa[p].z), f2tf32(pa[p].w) };
            *(uint4*)&As[row][lf] = ua;
            uint4 ub = { f2tf32(pb[p].x), f2tf32(pb[p].y), f2tf32(pb[p].z), f2tf32(pb[p].w) };
            *(uint4*)&Bs[row][lf] = ub;
        }
        __syncthreads();
        if (kc + 32 < 256) {
            #pragma unroll
            for (int p = 0; p < 2; p++) {
                pa[p] = *(const float4*)(sp  + (size_t)(lrow + p*32) * Cc + kc + 32 + lf);
                pb[p] = *(const float4*)(wvp + (size_t)(lrow + p*32) * Cc + kc + 32 + lf);
            }
        }
        #pragma unroll
        for (int k8 = 0; k8 < 4; k8++) {
            const int kb = k8 * 8;
            uint32_t afr[2][4];
            #pragma unroll
            for (int mi = 0; mi < 2; mi++) {
                int mr = wm * 32 + mi * 16;
                afr[mi][0] = As[mr + g4    ][kb + l4];
                afr[mi][1] = As[mr + g4 + 8][kb + l4];
                afr[mi][2] = As[mr + g4    ][kb + l4 + 4];
                afr[mi][3] = As[mr + g4 + 8][kb + l4 + 4];
            }
            uint32_t bfr[2][2];
            #pragma unroll
            for (int ni = 0; ni < 2; ni++) {
                int nr = wn * 16 + ni * 8 + g4;
                bfr[ni][0] = Bs[nr][kb + l4];
                bfr[ni][1] = Bs[nr][kb + l4 + 4];
            }
            #pragma unroll
            for (int mi = 0; mi < 2; mi++)
                #pragma unroll
                for (int ni = 0; ni < 2; ni++)
                    mma_tf32(acc[mi][ni], afr[mi], bfr[ni]);
        }
    }

    #pragma unroll
    for (int mi = 0; mi < 2; mi++) {
        #pragma unroll
        for (int h = 0; h < 2; h++) {
            const int m = wm * 32 + mi * 16 + h * 8 + g4;
            float* kvrow = g_KV + (size_t)(b*Mm + m) * Cc;
            #pragma unroll
            for (int ni = 0; ni < 2; ni++) {
                int c = c0 + wn * 16 + ni * 8 + l4 * 2;
                atomicAdd(kvrow + c,     acc[mi][ni][h*2 + 0]);
                atomicAdd(kvrow + c + 1, acc[mi][ni][h*2 + 1]);
            }
        }
    }
}

// ---------------- kernel: out = x + gamma * norm * (KV^T @ Qf), gate/bv folded into load ----------------
#define OSTR_N 136
#define OSTR_C 264
#define OUT_SMEM ((64*OSTR_N + 64*OSTR_C + 64 + 128) * 4)
__global__ __launch_bounds__(512) void out_mma_kernel(const float* __restrict__ x,
                                                      const float* __restrict__ gamma,
                                                      const float* __restrict__ bv,
                                                      float* __restrict__ out) {
    extern __shared__ uint32_t osm[];
    uint32_t* Qs  = osm;                           // [64][136]
    uint32_t* KVs = osm + 64 * OSTR_N;             // [64][264]
    float* ks_s   = (float*)(osm + 64*OSTR_N + 64*OSTR_C);  // [64]
    float* nrm_s  = ks_s + 64;                               // [128]

    const int tid = threadIdx.x;
    const int wid = tid >> 5;
    const int lid = tid & 31;
    const int g4  = lid >> 2;
    const int l4  = lid & 3;
    const int wm  = wid >> 2;          // 0..3  (c, 64 each)
    const int wn  = wid & 3;           // 0..3  (n, 32 each)

    const int n0 = blockIdx.x * 128;
    const int c0 = blockIdx.y * 256;
    const int b  = blockIdx.z;

    const float* qb  = g_Qf + (size_t)b * Mm * Nn;
    const float* kvb = g_KV + (size_t)b * Mm * Cc;

    #pragma unroll
    for (int p = 0; p < 4; p++) {
        int idx = tid + p * 512;
        int row = idx >> 5;
        int c4  = (idx & 31) * 4;
        float4 q = *(const float4*)(qb + (size_t)row * Nn + n0 + c4);
        uint4 uq = { f2tf32(q.x), f2tf32(q.y), f2tf32(q.z), f2tf32(q.w) };
        *(uint4*)&Qs[row * OSTR_N + c4] = uq;
    }
    // KV load with fused epilogue: KV = gate[c] * (KVraw + Ks2[m]*bv[c])
    #pragma unroll
    for (int p = 0; p < 8; p++) {
        int idx = tid + p * 512;
        int row = idx >> 6;
        int c4  = (idx & 63) * 4;
        const int cg = c0 + c4;
        float4 kv = *(const float4*)(kvb + (size_t)row * Cc + cg);
        float ks  = g_Ks2[b*Mm + row];
        float4 bvv = *(const float4*)(bv + cg);
        float4 gm = *(const float4*)(g_gmax + b*Cc + cg);
        float4 gs = *(const float4*)(g_gsum + b*Cc + cg);
        float v0 = (gm.x + gs.x * (1.f/Nn)) * (kv.x + ks * bvv.x);
        float v1 = (gm.y + gs.y * (1.f/Nn)) * (kv.y + ks * bvv.y);
        float v2 = (gm.z + gs.z * (1.f/Nn)) * (kv.z + ks * bvv.z);
        float v3 = (gm.w + gs.w * (1.f/Nn)) * (kv.w + ks * bvv.w);
        uint4 uk = { f2tf32(v0), f2tf32(v1), f2tf32(v2), f2tf32(v3) };
        *(uint4*)&KVs[row * OSTR_C + c4] = uk;
    }
    if (tid < 64) ks_s[tid] = g_Ks2[b*Mm + tid] + EPSc;
    __syncthreads();

    if (tid < 128) {
        float s = 0.f;
        #pragma unroll
        for (int m = 0; m < Mm; m++)
            s = fmaf(__uint_as_float(Qs[m * OSTR_N + tid]), ks_s[m], s);
        nrm_s[tid] = 1.f / s;
    }
    __syncthreads();

    float acc[4][4][4];
    #pragma unroll
    for (int mi = 0; mi < 4; mi++)
        #pragma unroll
        for (int ni = 0; ni < 4; ni++)
            #pragma unroll
            for (int q = 0; q < 4; q++) acc[mi][ni][q] = 0.f;

    #pragma unroll
    for (int k8 = 0; k8 < 8; k8++) {
        const int kb = k8 * 8;
        uint32_t afr[4][4];
        #pragma unroll
        for (int mi = 0; mi < 4; mi++) {
            int cr = wm * 64 + mi * 16;
            afr[mi][0] = KVs[(kb + l4    ) * OSTR_C + cr + g4];
            afr[mi][1] = KVs[(kb + l4    ) * OSTR_C + cr + g4 + 8];
            afr[mi][2] = KVs[(kb + l4 + 4) * OSTR_C + cr + g4];
            afr[mi][3] = KVs[(kb + l4 + 4) * OSTR_C + cr + g4 + 8];
        }
        uint32_t bfr[4][2];
        #pragma unroll
        for (int ni = 0; ni < 4; ni++) {
            int nr = wn * 32 + ni * 8 + g4;
            bfr[ni][0] = Qs[(kb + l4    ) * OSTR_N + nr];
            bfr[ni][1] = Qs[(kb + l4 + 4) * OSTR_N + nr];
        }
        #pragma unroll
        for (int mi = 0; mi < 4; mi++)
            #pragma unroll
            for (int ni = 0; ni < 4; ni++)
                mma_tf32(acc[mi][ni], afr[mi], bfr[ni]);
    }

    const float g = gamma[0];
    float2 nrm[4];
    #pragma unroll
    for (int ni = 0; ni < 4; ni++)
        nrm[ni] = *(float2*)&nrm_s[wn*32 + ni*8 + l4*2];

    #pragma unroll
    for (int mi = 0; mi < 4; mi++) {
        #pragma unroll
        for (int h = 0; h < 2; h++) {
            const int c = c0 + wm * 64 + mi * 16 + h * 8 + g4;
            const size_t off = ((size_t)(b * Cc + c)) * Nn + n0;
            #pragma unroll
            for (int ni = 0; ni < 4; ni++) {
                int ncol = wn * 32 + ni * 8 + l4 * 2;
                float2 xv = *(const float2*)(x + off + ncol);
                float2 r;
                r.x = xv.x + g * nrm[ni].x * acc[mi][ni][h*2 + 0];
                r.y = xv.y + g * nrm[ni].y * acc[mi][ni][h*2 + 1];
                *(float2*)(out + off + ncol) = r;
            }
        }
    }
}

// ---------------- launch (single stream) ----------------
extern "C" void kernel_launch(void* const* d_in, const int* in_sizes, int n_in,
                              void* d_out, int out_size) {
    const float* x     = (const float*)d_in[0];
    const float* wq    = (const float*)d_in[1];
    const float* bq    = (const float*)d_in[2];
    const float* wk    = (const float*)d_in[3];
    const float* bk    = (const float*)d_in[4];
    const float* wv    = (const float*)d_in[5];
    const float* bv    = (const float*)d_in[6];
    const float* gamma = (const float*)d_in[7];
    float* out = (float*)d_out;

    cudaFuncSetAttribute(out_mma_kernel, cudaFuncAttributeMaxDynamicSharedMemorySize, OUT_SMEM);

    zero_kernel<<<(Bz*Mm*Cc + 255) / 256, 256>>>();
    qk_mma_kernel<<<dim3(Nn/128, Bz), 256>>>(x, wq, bq, wk, bk);
    s_mma_kernel<<<dim3(8, Cc/128, Bz), 256>>>(x);
    kv2_kernel<<<dim3(Cc/64, 2, Bz), 256>>>(wv);
    out_mma_kernel<<<dim3(Nn/128, Cc/256, Bz), 512, OUT_SMEM>>>(x, gamma, bv, out);
}

// round 12
// speedup vs baseline: 1.1678x; 1.0691x over previous
#include <cuda_runtime.h>
#include <math.h>
#include <stdint.h>

#define Bz   8
#define Cc   512
#define Nn   4096
#define Mm   64
#define EPSc 1e-6f

// ---------------- device scratch ----------------
__device__ float g_Qf[Bz*Mm*Nn];   // softplus(Q)  [b][m][n]
__device__ float g_Kf[Bz*Mm*Nn];   // softplus(K)  [b][m][n]
__device__ float g_S [Bz*Mm*Cc];   // Kf . x^T     [b][m][c']
__device__ float g_KV[Bz*Mm*Cc];   // RAW S.Wv^T accumulator [b][m][c]
__device__ float g_Ks2[Bz*Mm];     // sum_n Kf
__device__ float g_gmax[Bz*Cc];
__device__ float g_gsum[Bz*Cc];

// ---------------- helpers ----------------
// NOTE: tf32 mma operands are passed as raw f32 bits (hardware truncates the
// mantissa). This skips cvt.rna and costs <=2^-10 relative per operand.
__device__ __forceinline__ void mma_tf32(float* d, const uint32_t* a, const uint32_t* b) {
    asm volatile(
        "mma.sync.aligned.m16n8k8.row.col.f32.tf32.tf32.f32 "
        "{%0,%1,%2,%3}, {%4,%5,%6,%7}, {%8,%9}, {%0,%1,%2,%3};"
        : "+f"(d[0]), "+f"(d[1]), "+f"(d[2]), "+f"(d[3])
        : "r"(a[0]), "r"(a[1]), "r"(a[2]), "r"(a[3]), "r"(b[0]), "r"(b[1]));
}
__device__ __forceinline__ void atomicMaxF(float* addr, float v) {
    if (v >= 0.f) atomicMax((int*)addr, __float_as_int(v));
    else          atomicMin((unsigned int*)addr, __float_as_uint(v));
}
__device__ __forceinline__ float softplus_f(float v) {
    return fmaxf(v, 0.f) + __logf(1.f + __expf(-fabsf(v)));
}

// ---------------- kernel: zero scratch ----------------
__global__ void zero_kernel() {
    int i = blockIdx.x * 256 + threadIdx.x;
    if (i < Bz*Mm*Cc) { g_S[i] = 0.f; g_KV[i] = 0.f; }
    if (i < Bz*Mm) g_Ks2[i] = 0.f;
    if (i < Bz*Cc) { g_gmax[i] = -INFINITY; g_gsum[i] = 0.f; }
}

// ---------------- kernel: Q,K projection GEMM (tf32 mma, double-buffered) ----------------
// D[r][n] = sum_c W[r][c] * x[b][c][n], r in [0,128): rows 0..63 wq, 64..127 wk
#define QK_STG (128*36 + 32*132)
#define QK_SMEM (2 * QK_STG * 4)
__global__ __launch_bounds__(256, 2) void qk_mma_kernel(
    const float* __restrict__ x,
    const float* __restrict__ wq, const float* __restrict__ bq,
    const float* __restrict__ wk, const float* __restrict__ bk)
{
    extern __shared__ float qsm[];

    const int tid = threadIdx.x;
    const int wid = tid >> 5;
    const int lid = tid & 31;
    const int g4  = lid >> 2;
    const int l4  = lid & 3;
    const int wm  = wid >> 1;          // 0..3 over r
    const int wn  = wid & 1;           // 0..1 over n

    const int n0 = blockIdx.x * 128;
    const int b  = blockIdx.y;

    const float* xb = x + (size_t)b * Cc * Nn;

    float acc[2][8][4];
    #pragma unroll
    for (int mi = 0; mi < 2; mi++)
        #pragma unroll
        for (int ni = 0; ni < 8; ni++)
            #pragma unroll
            for (int q = 0; q < 4; q++) acc[mi][ni][q] = 0.f;

    const int lrow = tid >> 3;          // 0..31
    const int lf   = (tid & 7) * 4;

    // A-row source pointers (fixed per thread)
    const float* wsrc[4];
    #pragma unroll
    for (int p = 0; p < 4; p++) {
        int row = lrow + p * 32;
        wsrc[p] = (row < Mm) ? (wq + (size_t)row * Cc) : (wk + (size_t)(row - Mm) * Cc);
    }

    // preload chunk 0 into stage 0
    {
        float* As0 = qsm;
        float* Xs0 = qsm + 128 * 36;
        #pragma unroll
        for (int p = 0; p < 4; p++) {
            int row = lrow + p * 32;
            *(float4*)&As0[row * 36 + lf] = *(const float4*)(wsrc[p] + lf);
            int idx = tid + p * 256;
            *(float4*)&Xs0[(idx >> 5) * 132 + (idx & 31) * 4] =
                *(const float4*)(xb + (size_t)(idx >> 5) * Nn + n0 + (idx & 31) * 4);
        }
    }
    __syncthreads();

    for (int kc = 0; kc < Cc; kc += 32) {
        const int st = (kc >> 5) & 1;
        const float* Asb = qsm + st * QK_STG;
        const float* Xsb = Asb + 128 * 36;
        const bool more = (kc + 32 < Cc);

        float4 va[4], vb[4];
        if (more) {
            #pragma unroll
            for (int p = 0; p < 4; p++) {
                va[p] = *(const float4*)(wsrc[p] + kc + 32 + lf);
                int idx = tid + p * 256;
                vb[p] = *(const float4*)(xb + (size_t)(kc + 32 + (idx >> 5)) * Nn + n0 + (idx & 31) * 4);
            }
        }

        #pragma unroll
        for (int k8 = 0; k8 < 4; k8++) {
            const int kb = k8 * 8;
            uint32_t afr[2][4];
            #pragma unroll
            for (int mi = 0; mi < 2; mi++) {
                int mr = wm * 32 + mi * 16;
                afr[mi][0] = __float_as_uint(Asb[(mr + g4    ) * 36 + kb + l4]);
                afr[mi][1] = __float_as_uint(Asb[(mr + g4 + 8) * 36 + kb + l4]);
                afr[mi][2] = __float_as_uint(Asb[(mr + g4    ) * 36 + kb + l4 + 4]);
                afr[mi][3] = __float_as_uint(Asb[(mr + g4 + 8) * 36 + kb + l4 + 4]);
            }
            uint32_t bfr[8][2];
            #pragma unroll
            for (int ni = 0; ni < 8; ni++) {
                int nr = wn * 64 + ni * 8 + g4;
                bfr[ni][0] = __float_as_uint(Xsb[(kb + l4    ) * 132 + nr]);
                bfr[ni][1] = __float_as_uint(Xsb[(kb + l4 + 4) * 132 + nr]);
            }
            #pragma unroll
            for (int mi = 0; mi < 2; mi++)
                #pragma unroll
                for (int ni = 0; ni < 8; ni++)
                    mma_tf32(acc[mi][ni], afr[mi], bfr[ni]);
        }

        if (more) {
            float* Asn = qsm + (1 - st) * QK_STG;
            float* Xsn = Asn + 128 * 36;
            #pragma unroll
            for (int p = 0; p < 4; p++) {
                int row = lrow + p * 32;
                *(float4*)&Asn[row * 36 + lf] = va[p];
                int idx = tid + p * 256;
                *(float4*)&Xsn[(idx >> 5) * 132 + (idx & 31) * 4] = vb[p];
            }
        }
        __syncthreads();
    }

    // epilogue: bias + softplus; ksum for K rows
    #pragma unroll
    for (int mi = 0; mi < 2; mi++) {
        #pragma unroll
        for (int h = 0; h < 2; h++) {
            const int r = wm * 32 + mi * 16 + h * 8 + g4;
            float bias; float* dst; bool isK;
            if (r < Mm) { bias = bq[r];      dst = g_Qf + (size_t)(b*Mm + r) * Nn;      isK = false; }
            else        { bias = bk[r - Mm]; dst = g_Kf + (size_t)(b*Mm + r - Mm) * Nn; isK = true;  }
            float ks = 0.f;
            #pragma unroll
            for (int ni = 0; ni < 8; ni++) {
                float v0 = softplus_f(acc[mi][ni][h*2 + 0] + bias);
                float v1 = softplus_f(acc[mi][ni][h*2 + 1] + bias);
                if (isK) ks += v0 + v1;
                float2 w2 = { v0, v1 };
                *(float2*)(dst + n0 + wn * 64 + ni * 8 + l4 * 2) = w2;
            }
            if (isK) {
                ks += __shfl_xor_sync(0xffffffffu, ks, 1);
                ks += __shfl_xor_sync(0xffffffffu, ks, 2);
                if (l4 == 0) atomicAdd(&g_Ks2[b*Mm + (r - Mm)], ks);
            }
        }
    }
}

// ---------------- kernel: S = Kf . x^T (split-k over n, double-buffered) + gate partials ----------------
#define S_STG (64*36 + 128*36)
#define S_SMEM (2 * S_STG * 4)
__global__ __launch_bounds__(256, 2) void s_mma_kernel(const float* __restrict__ x) {
    extern __shared__ float ssm[];

    const int tid = threadIdx.x;
    const int wid = tid >> 5;
    const int lid = tid & 31;
    const int g4  = lid >> 2;
    const int l4  = lid & 3;
    const int wm  = wid >> 2;          // 0..1
    const int wn  = wid & 3;           // 0..3

    const int b     = blockIdx.z;
    const int c0    = blockIdx.y * 128;
    const int nbase = blockIdx.x * 512;

    const float* kf = g_Kf + (size_t)b * Mm * Nn + nbase;
    const float* xp = x + ((size_t)(b*Cc + c0)) * Nn + nbase;

    float acc[2][4][4];
    #pragma unroll
    for (int mi = 0; mi < 2; mi++)
        #pragma unroll
        for (int ni = 0; ni < 4; ni++)
            #pragma unroll
            for (int q = 0; q < 4; q++) acc[mi][ni][q] = 0.f;

    float gmx[4] = {-INFINITY, -INFINITY, -INFINITY, -INFINITY};
    float gsm[4] = {0.f, 0.f, 0.f, 0.f};

    const int lrow = tid >> 3;
    const int lf   = (tid & 7) * 4;

    // preload chunk 0 into stage 0 (with gate update)
    {
        float* As0 = ssm;
        float* Bs0 = ssm + 64 * 36;
        #pragma unroll
        for (int p = 0; p < 2; p++) {
            int row = lrow + p * 32;
            *(float4*)&As0[row * 36 + lf] = *(const float4*)(kf + (size_t)row * Nn + lf);
        }
        #pragma unroll
        for (int p = 0; p < 4; p++) {
            int row = lrow + p * 32;
            float4 v = *(const float4*)(xp + (size_t)row * Nn + lf);
            gmx[p] = fmaxf(gmx[p], fmaxf(fmaxf(v.x, v.y), fmaxf(v.z, v.w)));
            gsm[p] += (v.x + v.y) + (v.z + v.w);
            *(float4*)&Bs0[row * 36 + lf] = v;
        }
    }
    __syncthreads();

    for (int nc = 0; nc < 512; nc += 32) {
        const int st = (nc >> 5) & 1;
        const float* Asb = ssm + st * S_STG;
        const float* Bsb = Asb + 64 * 36;
        const bool more = (nc + 32 < 512);

        float4 pa[2], pb[4];
        if (more) {
            #pragma unroll
            for (int p = 0; p < 2; p++)
                pa[p] = *(const float4*)(kf + (size_t)(lrow + p*32) * Nn + nc + 32 + lf);
            #pragma unroll
            for (int p = 0; p < 4; p++)
                pb[p] = *(const float4*)(xp + (size_t)(lrow + p*32) * Nn + nc + 32 + lf);
        }

        #pragma unroll
        for (int k8 = 0; k8 < 4; k8++) {
            const int kb = k8 * 8;
            uint32_t afr[2][4];
            #pragma unroll
            for (int mi = 0; mi < 2; mi++) {
                int mr = wm * 32 + mi * 16;
                afr[mi][0] = __float_as_uint(Asb[(mr + g4    ) * 36 + kb + l4]);
                afr[mi][1] = __float_as_uint(Asb[(mr + g4 + 8) * 36 + kb + l4]);
                afr[mi][2] = __float_as_uint(Asb[(mr + g4    ) * 36 + kb + l4 + 4]);
                afr[mi][3] = __float_as_uint(Asb[(mr + g4 + 8) * 36 + kb + l4 + 4]);
            }
            uint32_t bfr[4][2];
            #pragma unroll
            for (int ni = 0; ni < 4; ni++) {
                int nr = wn * 32 + ni * 8 + g4;
                bfr[ni][0] = __float_as_uint(Bsb[nr * 36 + kb + l4]);
                bfr[ni][1] = __float_as_uint(Bsb[nr * 36 + kb + l4 + 4]);
            }
            #pragma unroll
            for (int mi = 0; mi < 2; mi++)
                #pragma unroll
                for (int ni = 0; ni < 4; ni++)
                    mma_tf32(acc[mi][ni], afr[mi], bfr[ni]);
        }

        if (more) {
            float* Asn = ssm + (1 - st) * S_STG;
            float* Bsn = Asn + 64 * 36;
            #pragma unroll
            for (int p = 0; p < 2; p++)
                *(float4*)&Asn[(lrow + p*32) * 36 + lf] = pa[p];
            #pragma unroll
            for (int p = 0; p < 4; p++) {
                float4 v = pb[p];
                gmx[p] = fmaxf(gmx[p], fmaxf(fmaxf(v.x, v.y), fmaxf(v.z, v.w)));
                gsm[p] += (v.x + v.y) + (v.z + v.w);
                *(float4*)&Bsn[(lrow + p*32) * 36 + lf] = v;
            }
        }
        __syncthreads();
    }

    // gate partials: reduce across the 8 lanes sharing each loaded row
    #pragma unroll
    for (int p = 0; p < 4; p++) {
        float mx = gmx[p], sm = gsm[p];
        #pragma unroll
        for (int o = 1; o < 8; o <<= 1) {
            mx = fmaxf(mx, __shfl_xor_sync(0xffffffffu, mx, o));
            sm += __shfl_xor_sync(0xffffffffu, sm, o);
        }
        if ((lid & 7) == 0) {
            int c = c0 + lrow + p * 32;
            atomicMaxF(&g_gmax[b*Cc + c], mx);
            atomicAdd(&g_gsum[b*Cc + c], sm);
        }
    }

    // accumulate S
    #pragma unroll
    for (int mi = 0; mi < 2; mi++) {
        #pragma unroll
        for (int h = 0; h < 2; h++) {
            const int m = wm * 32 + mi * 16 + h * 8 + g4;
            float* srow = g_S + (size_t)(b*Mm + m) * Cc + c0;
            #pragma unroll
            for (int ni = 0; ni < 4; ni++) {
                int c = wn * 32 + ni * 8 + l4 * 2;
                atomicAdd(srow + c,     acc[mi][ni][h*2 + 0]);
                atomicAdd(srow + c + 1, acc[mi][ni][h*2 + 1]);
            }
        }
    }
}

// ---------------- kernel: KVraw += S . Wv^T  (split-k x4, prefetched) ----------------
__global__ __launch_bounds__(256, 2) void kv2_kernel(const float* __restrict__ wv) {
    __shared__ float As[64][36];    // [m][k]
    __shared__ float Bs[64][36];    // [c][k]

    const int tid = threadIdx.x;
    const int wid = tid >> 5;
    const int lid = tid & 31;
    const int g4  = lid >> 2;
    const int l4  = lid & 3;
    const int wm  = wid >> 2;          // 0..1
    const int wn  = wid & 3;           // 0..3

    const int c0 = blockIdx.x * 64;
    const int kh = blockIdx.y * 128;   // k-quarter base
    const int b  = blockIdx.z;

    const float* sp  = g_S + (size_t)b * Mm * Cc + kh;
    const float* wvp = wv + (size_t)c0 * Cc + kh;

    float acc[2][2][4];
    #pragma unroll
    for (int mi = 0; mi < 2; mi++)
        #pragma unroll
        for (int ni = 0; ni < 2; ni++)
            #pragma unroll
            for (int q = 0; q < 4; q++) acc[mi][ni][q] = 0.f;

    const int lrow = tid >> 3;          // 0..31
    const int lf   = (tid & 7) * 4;

    float4 pa[2], pb[2];
    #pragma unroll
    for (int p = 0; p < 2; p++) {
        pa[p] = *(const float4*)(sp  + (size_t)(lrow + p*32) * Cc + lf);
        pb[p] = *(const float4*)(wvp + (size_t)(lrow + p*32) * Cc + lf);
    }

    for (int kc = 0; kc < 128; kc += 32) {
        if (kc) __syncthreads();
        #pragma unroll
        for (int p = 0; p < 2; p++) {
            int row = lrow + p * 32;
            *(float4*)&As[row][lf] = pa[p];
            *(float4*)&Bs[row][lf] = pb[p];
        }
        __syncthreads();
        if (kc + 32 < 128) {
            #pragma unroll
            for (int p = 0; p < 2; p++) {
                pa[p] = *(const float4*)(sp  + (size_t)(lrow + p*32) * Cc + kc + 32 + lf);
                pb[p] = *(const float4*)(wvp + (size_t)(lrow + p*32) * Cc + kc + 32 + lf);
            }
        }
        #pragma unroll
        for (int k8 = 0; k8 < 4; k8++) {
            const int kb = k8 * 8;
            uint32_t afr[2][4];
            #pragma unroll
            for (int mi = 0; mi < 2; mi++) {
                int mr = wm * 32 + mi * 16;
                afr[mi][0] = __float_as_uint(As[mr + g4    ][kb + l4]);
                afr[mi][1] = __float_as_uint(As[mr + g4 + 8][kb + l4]);
                afr[mi][2] = __float_as_uint(As[mr + g4    ][kb + l4 + 4]);
                afr[mi][3] = __float_as_uint(As[mr + g4 + 8][kb + l4 + 4]);
            }
            uint32_t bfr[2][2];
            #pragma unroll
            for (int ni = 0; ni < 2; ni++) {
                int nr = wn * 16 + ni * 8 + g4;
                bfr[ni][0] = __float_as_uint(Bs[nr][kb + l4]);
                bfr[ni][1] = __float_as_uint(Bs[nr][kb + l4 + 4]);
            }
            #pragma unroll
            for (int mi = 0; mi < 2; mi++)
                #pragma unroll
                for (int ni = 0; ni < 2; ni++)
                    mma_tf32(acc[mi][ni], afr[mi], bfr[ni]);
        }
    }

    #pragma unroll
    for (int mi = 0; mi < 2; mi++) {
        #pragma unroll
        for (int h = 0; h < 2; h++) {
            const int m = wm * 32 + mi * 16 + h * 8 + g4;
            float* kvrow = g_KV + (size_t)(b*Mm + m) * Cc;
            #pragma unroll
            for (int ni = 0; ni < 2; ni++) {
                int c = c0 + wn * 16 + ni * 8 + l4 * 2;
                atomicAdd(kvrow + c,     acc[mi][ni][h*2 + 0]);
                atomicAdd(kvrow + c + 1, acc[mi][ni][h*2 + 1]);
            }
        }
    }
}

// ---------------- kernel: out = x + gamma * norm * (KV^T @ Qf), gate/bv folded into load ----------------
#define OSTR_N 136
#define OSTR_C 264
#define OUT_SMEM ((64*OSTR_N + 64*OSTR_C + 64 + 128) * 4)
__global__ __launch_bounds__(512) void out_mma_kernel(const float* __restrict__ x,
                                                      const float* __restrict__ gamma,
                                                      const float* __restrict__ bv,
                                                      float* __restrict__ out) {
    extern __shared__ float osm[];
    float* Qs  = osm;                           // [64][136]
    float* KVs = osm + 64 * OSTR_N;             // [64][264]
    float* ks_s   = osm + 64*OSTR_N + 64*OSTR_C;  // [64]
    float* nrm_s  = ks_s + 64;                    // [128]

    const int tid = threadIdx.x;
    const int wid = tid >> 5;
    const int lid = tid & 31;
    const int g4  = lid >> 2;
    const int l4  = lid & 3;
    const int wm  = wid >> 2;          // 0..3  (c, 64 each)
    const int wn  = wid & 3;           // 0..3  (n, 32 each)

    const int n0 = blockIdx.x * 128;
    const int c0 = blockIdx.y * 256;
    const int b  = blockIdx.z;

    const float* qb  = g_Qf + (size_t)b * Mm * Nn;
    const float* kvb = g_KV + (size_t)b * Mm * Cc;

    #pragma unroll
    for (int p = 0; p < 4; p++) {
        int idx = tid + p * 512;
        int row = idx >> 5;
        int c4  = (idx & 31) * 4;
        *(float4*)&Qs[row * OSTR_N + c4] =
            *(const float4*)(qb + (size_t)row * Nn + n0 + c4);
    }
    // KV load with fused epilogue: KV = gate[c] * (KVraw + Ks2[m]*bv[c])
    #pragma unroll
    for (int p = 0; p < 8; p++) {
        int idx = tid + p * 512;
        int row = idx >> 6;
        int c4  = (idx & 63) * 4;
        const int cg = c0 + c4;
        float4 kv = *(const float4*)(kvb + (size_t)row * Cc + cg);
        float ks  = g_Ks2[b*Mm + row];
        float4 bvv = *(const float4*)(bv + cg);
        float4 gm = *(const float4*)(g_gmax + b*Cc + cg);
        float4 gs = *(const float4*)(g_gsum + b*Cc + cg);
        float4 w;
        w.x = (gm.x + gs.x * (1.f/Nn)) * (kv.x + ks * bvv.x);
        w.y = (gm.y + gs.y * (1.f/Nn)) * (kv.y + ks * bvv.y);
        w.z = (gm.z + gs.z * (1.f/Nn)) * (kv.z + ks * bvv.z);
        w.w = (gm.w + gs.w * (1.f/Nn)) * (kv.w + ks * bvv.w);
        *(float4*)&KVs[row * OSTR_C + c4] = w;
    }
    if (tid < 64) ks_s[tid] = g_Ks2[b*Mm + tid] + EPSc;
    __syncthreads();

    if (tid < 128) {
        float s = 0.f;
        #pragma unroll
        for (int m = 0; m < Mm; m++)
            s = fmaf(Qs[m * OSTR_N + tid], ks_s[m], s);
        nrm_s[tid] = 1.f / s;
    }
    __syncthreads();

    float acc[4][4][4];
    #pragma unroll
    for (int mi = 0; mi < 4; mi++)
        #pragma unroll
        for (int ni = 0; ni < 4; ni++)
            #pragma unroll
            for (int q = 0; q < 4; q++) acc[mi][ni][q] = 0.f;

    #pragma unroll
    for (int k8 = 0; k8 < 8; k8++) {
        const int kb = k8 * 8;
        uint32_t afr[4][4];
        #pragma unroll
        for (int mi = 0; mi < 4; mi++) {
            int cr = wm * 64 + mi * 16;
            afr[mi][0] = __float_as_uint(KVs[(kb + l4    ) * OSTR_C + cr + g4]);
            afr[mi][1] = __float_as_uint(KVs[(kb + l4    ) * OSTR_C + cr + g4 + 8]);
            afr[mi][2] = __float_as_uint(KVs[(kb + l4 + 4) * OSTR_C + cr + g4]);
            afr[mi][3] = __float_as_uint(KVs[(kb + l4 + 4) * OSTR_C + cr + g4 + 8]);
        }
        uint32_t bfr[4][2];
        #pragma unroll
        for (int ni = 0; ni < 4; ni++) {
            int nr = wn * 32 + ni * 8 + g4;
            bfr[ni][0] = __float_as_uint(Qs[(kb + l4    ) * OSTR_N + nr]);
            bfr[ni][1] = __float_as_uint(Qs[(kb + l4 + 4) * OSTR_N + nr]);
        }
        #pragma unroll
        for (int mi = 0; mi < 4; mi++)
            #pragma unroll
            for (int ni = 0; ni < 4; ni++)
                mma_tf32(acc[mi][ni], afr[mi], bfr[ni]);
    }

    const float g = gamma[0];
    float2 nrm[4];
    #pragma unroll
    for (int ni = 0; ni < 4; ni++)
        nrm[ni] = *(float2*)&nrm_s[wn*32 + ni*8 + l4*2];

    #pragma unroll
    for (int mi = 0; mi < 4; mi++) {
        #pragma unroll
        for (int h = 0; h < 2; h++) {
            const int c = c0 + wm * 64 + mi * 16 + h * 8 + g4;
            const size_t off = ((size_t)(b * Cc + c)) * Nn + n0;
            #pragma unroll
            for (int ni = 0; ni < 4; ni++) {
                int ncol = wn * 32 + ni * 8 + l4 * 2;
                float2 xv = *(const float2*)(x + off + ncol);
                float2 r;
                r.x = xv.x + g * nrm[ni].x * acc[mi][ni][h*2 + 0];
                r.y = xv.y + g * nrm[ni].y * acc[mi][ni][h*2 + 1];
                *(float2*)(out + off + ncol) = r;
            }
        }
    }
}

// ---------------- launch (single stream) ----------------
extern "C" void kernel_launch(void* const* d_in, const int* in_sizes, int n_in,
                              void* d_out, int out_size) {
    const float* x     = (const float*)d_in[0];
    const float* wq    = (const float*)d_in[1];
    const float* bq    = (const float*)d_in[2];
    const float* wk    = (const float*)d_in[3];
    const float* bk    = (const float*)d_in[4];
    const float* wv    = (const float*)d_in[5];
    const float* bv    = (const float*)d_in[6];
    const float* gamma = (const float*)d_in[7];
    float* out = (float*)d_out;

    cudaFuncSetAttribute(qk_mma_kernel, cudaFuncAttributeMaxDynamicSharedMemorySize, QK_SMEM);
    cudaFuncSetAttribute(s_mma_kernel, cudaFuncAttributeMaxDynamicSharedMemorySize, S_SMEM);
    cudaFuncSetAttribute(out_mma_kernel, cudaFuncAttributeMaxDynamicSharedMemorySize, OUT_SMEM);

    zero_kernel<<<(Bz*Mm*Cc + 255) / 256, 256>>>();
    qk_mma_kernel<<<dim3(Nn/128, Bz), 256, QK_SMEM>>>(x, wq, bq, wk, bk);
    s_mma_kernel<<<dim3(8, Cc/128, Bz), 256, S_SMEM>>>(x);
    kv2_kernel<<<dim3(Cc/64, 4, Bz), 256>>>(wv);
    out_mma_kernel<<<dim3(Nn/128, Cc/256, Bz), 512, OUT_SMEM>>>(x, gamma, bv, out);
}

// round 14
// speedup vs baseline: 1.3148x; 1.1259x over previous
#include <cuda_runtime.h>
#include <math.h>
#include <stdint.h>

#define Bz   8
#define Cc   512
#define Nn   4096
#define Mm   64
#define EPSc 1e-6f

// ---------------- device scratch ----------------
__device__ float g_Qf[Bz*Mm*Nn];   // softplus(Q)  [b][m][n]
__device__ float g_Kf[Bz*Mm*Nn];   // softplus(K)  [b][m][n]
__device__ float g_S [Bz*Mm*Cc];   // Kf . x^T     [b][m][c']
__device__ float g_KV[Bz*Mm*Cc];   // RAW S.Wv^T accumulator [b][m][c]
__device__ float g_Ks2[Bz*Mm];     // sum_n Kf
__device__ float g_gmax[Bz*Cc];
__device__ float g_gsum[Bz*Cc];

// ---------------- helpers ----------------
__device__ __forceinline__ void mma_tf32(float* d, const uint32_t* a, const uint32_t* b) {
    asm volatile(
        "mma.sync.aligned.m16n8k8.row.col.f32.tf32.tf32.f32 "
        "{%0,%1,%2,%3}, {%4,%5,%6,%7}, {%8,%9}, {%0,%1,%2,%3};"
        : "+f"(d[0]), "+f"(d[1]), "+f"(d[2]), "+f"(d[3])
        : "r"(a[0]), "r"(a[1]), "r"(a[2]), "r"(a[3]), "r"(b[0]), "r"(b[1]));
}
__device__ __forceinline__ void mma_bf16(float* d, const uint32_t* a, const uint32_t* b) {
    asm volatile(
        "mma.sync.aligned.m16n8k16.row.col.f32.bf16.bf16.f32 "
        "{%0,%1,%2,%3}, {%4,%5,%6,%7}, {%8,%9}, {%0,%1,%2,%3};"
        : "+f"(d[0]), "+f"(d[1]), "+f"(d[2]), "+f"(d[3])
        : "r"(a[0]), "r"(a[1]), "r"(a[2]), "r"(a[3]), "r"(b[0]), "r"(b[1]));
}
// pack two f32 into bf16x2: lo = first (even k), hi = second (odd k)
__device__ __forceinline__ uint32_t pack_bf16(float lo, float hi) {
    uint32_t r;
    asm("cvt.rn.bf16x2.f32 %0, %1, %2;" : "=r"(r) : "f"(hi), "f"(lo));
    return r;
}
__device__ __forceinline__ void atomicMaxF(float* addr, float v) {
    if (v >= 0.f) atomicMax((int*)addr, __float_as_int(v));
    else          atomicMin((unsigned int*)addr, __float_as_uint(v));
}
__device__ __forceinline__ float softplus_f(float v) {
    return fmaxf(v, 0.f) + __logf(1.f + __expf(-fabsf(v)));
}

// ---------------- kernel: zero scratch ----------------
__global__ void zero_kernel() {
    int i = blockIdx.x * 256 + threadIdx.x;
    if (i < Bz*Mm*Cc) { g_S[i] = 0.f; g_KV[i] = 0.f; }
    if (i < Bz*Mm) g_Ks2[i] = 0.f;
    if (i < Bz*Cc) { g_gmax[i] = -INFINITY; g_gsum[i] = 0.f; }
}

// ---------------- kernel: Q,K projection GEMM (bf16 m16n8k16, double-buffered) ----------------
// D[r][n] = sum_c W[r][c] * x[b][c][n], r in [0,128): rows 0..63 wq, 64..127 wk
// Operands packed as bf16 pairs along k; fp32 accumulate.
#define QK_ASTR 20                       // packed words per A row (16 + pad 4)
#define QK_XSTR 132                      // packed-row stride for X (128 + pad 4)
#define QK_STG  (128*QK_ASTR + 16*QK_XSTR)   // words per stage
#define QK_SMEM (2 * QK_STG * 4)
__global__ __launch_bounds__(256, 2) void qk_mma_kernel(
    const float* __restrict__ x,
    const float* __restrict__ wq, const float* __restrict__ bq,
    const float* __restrict__ wk, const float* __restrict__ bk)
{
    extern __shared__ uint32_t qsm[];

    const int tid = threadIdx.x;
    const int wid = tid >> 5;
    const int lid = tid & 31;
    const int g4  = lid >> 2;
    const int l4  = lid & 3;
    const int wm  = wid >> 1;          // 0..3 over r
    const int wn  = wid & 1;           // 0..1 over n

    const int n0 = blockIdx.x * 128;
    const int b  = blockIdx.y;

    const float* xb = x + (size_t)b * Cc * Nn;

    float acc[2][8][4];
    #pragma unroll
    for (int mi = 0; mi < 2; mi++)
        #pragma unroll
        for (int ni = 0; ni < 8; ni++)
            #pragma unroll
            for (int q = 0; q < 4; q++) acc[mi][ni][q] = 0.f;

    const int lrow = tid >> 3;          // 0..31 (A loader row)
    const int lf   = (tid & 7) * 4;     // A loader float offset (0..28)

    // A-row source pointers (fixed per thread)
    const float* wsrc[4];
    #pragma unroll
    for (int p = 0; p < 4; p++) {
        int row = lrow + p * 32;
        wsrc[p] = (row < Mm) ? (wq + (size_t)row * Cc) : (wk + (size_t)(row - Mm) * Cc);
    }
    // B loader task: t = tid + p*256 (p<2), j = t>>5 (packed row 0..15), n4 = (t&31)*4
    const int bj0 = tid >> 5;           // p=0 packed row
    const int bn4 = (tid & 31) * 4;

    // preload chunk 0 into stage 0
    {
        uint32_t* As0 = qsm;
        uint32_t* Xs0 = qsm + 128 * QK_ASTR;
        #pragma unroll
        for (int p = 0; p < 4; p++) {
            int row = lrow + p * 32;
            float4 va = *(const float4*)(wsrc[p] + lf);
            As0[row * QK_ASTR + (lf >> 1)    ] = pack_bf16(va.x, va.y);
            As0[row * QK_ASTR + (lf >> 1) + 1] = pack_bf16(va.z, va.w);
        }
        #pragma unroll
        for (int p = 0; p < 2; p++) {
            int j = bj0 + p * 8;
            float4 r0 = *(const float4*)(xb + (size_t)(2*j    ) * Nn + n0 + bn4);
            float4 r1 = *(const float4*)(xb + (size_t)(2*j + 1) * Nn + n0 + bn4);
            uint4 w;
            w.x = pack_bf16(r0.x, r1.x);
            w.y = pack_bf16(r0.y, r1.y);
            w.z = pack_bf16(r0.z, r1.z);
            w.w = pack_bf16(r0.w, r1.w);
            *(uint4*)&Xs0[j * QK_XSTR + bn4] = w;
        }
    }
    __syncthreads();

    for (int kc = 0; kc < Cc; kc += 32) {
        const int st = (kc >> 5) & 1;
        const uint32_t* Asb = qsm + st * QK_STG;
        const uint32_t* Xsb = Asb + 128 * QK_ASTR;
        const bool more = (kc + 32 < Cc);

        float4 va[4], r0[2], r1[2];
        if (more) {
            #pragma unroll
            for (int p = 0; p < 4; p++)
                va[p] = *(const float4*)(wsrc[p] + kc + 32 + lf);
            #pragma unroll
            for (int p = 0; p < 2; p++) {
                int j = bj0 + p * 8;
                r0[p] = *(const float4*)(xb + (size_t)(kc + 32 + 2*j    ) * Nn + n0 + bn4);
                r1[p] = *(const float4*)(xb + (size_t)(kc + 32 + 2*j + 1) * Nn + n0 + bn4);
            }
        }

        #pragma unroll
        for (int s16 = 0; s16 < 2; s16++) {
            const int kb2 = s16 * 8;   // packed-row offset within stage
            uint32_t afr[2][4];
            #pragma unroll
            for (int mi = 0; mi < 2; mi++) {
                int mr = wm * 32 + mi * 16;
                afr[mi][0] = Asb[(mr + g4    ) * QK_ASTR + kb2 + l4];
                afr[mi][1] = Asb[(mr + g4 + 8) * QK_ASTR + kb2 + l4];
                afr[mi][2] = Asb[(mr + g4    ) * QK_ASTR + kb2 + l4 + 4];
                afr[mi][3] = Asb[(mr + g4 + 8) * QK_ASTR + kb2 + l4 + 4];
            }
            uint32_t bfr[8][2];
            #pragma unroll
            for (int ni = 0; ni < 8; ni++) {
                int nr = wn * 64 + ni * 8 + g4;
                bfr[ni][0] = Xsb[(kb2 + l4    ) * QK_XSTR + nr];
                bfr[ni][1] = Xsb[(kb2 + l4 + 4) * QK_XSTR + nr];
            }
            #pragma unroll
            for (int mi = 0; mi < 2; mi++)
                #pragma unroll
                for (int ni = 0; ni < 8; ni++)
                    mma_bf16(acc[mi][ni], afr[mi], bfr[ni]);
        }

        if (more) {
            uint32_t* Asn = qsm + (1 - st) * QK_STG;
            uint32_t* Xsn = Asn + 128 * QK_ASTR;
            #pragma unroll
            for (int p = 0; p < 4; p++) {
                int row = lrow + p * 32;
                Asn[row * QK_ASTR + (lf >> 1)    ] = pack_bf16(va[p].x, va[p].y);
                Asn[row * QK_ASTR + (lf >> 1) + 1] = pack_bf16(va[p].z, va[p].w);
            }
            #pragma unroll
            for (int p = 0; p < 2; p++) {
                int j = bj0 + p * 8;
                uint4 w;
                w.x = pack_bf16(r0[p].x, r1[p].x);
                w.y = pack_bf16(r0[p].y, r1[p].y);
                w.z = pack_bf16(r0[p].z, r1[p].z);
                w.w = pack_bf16(r0[p].w, r1[p].w);
                *(uint4*)&Xsn[j * QK_XSTR + bn4] = w;
            }
        }
        __syncthreads();
    }

    // epilogue: bias + softplus; ksum for K rows
    #pragma unroll
    for (int mi = 0; mi < 2; mi++) {
        #pragma unroll
        for (int h = 0; h < 2; h++) {
            const int r = wm * 32 + mi * 16 + h * 8 + g4;
            float bias; float* dst; bool isK;
            if (r < Mm) { bias = bq[r];      dst = g_Qf + (size_t)(b*Mm + r) * Nn;      isK = false; }
            else        { bias = bk[r - Mm]; dst = g_Kf + (size_t)(b*Mm + r - Mm) * Nn; isK = true;  }
            float ks = 0.f;
            #pragma unroll
            for (int ni = 0; ni < 8; ni++) {
                float v0 = softplus_f(acc[mi][ni][h*2 + 0] + bias);
                float v1 = softplus_f(acc[mi][ni][h*2 + 1] + bias);
                if (isK) ks += v0 + v1;
                float2 w2 = { v0, v1 };
                *(float2*)(dst + n0 + wn * 64 + ni * 8 + l4 * 2) = w2;
            }
            if (isK) {
                ks += __shfl_xor_sync(0xffffffffu, ks, 1);
                ks += __shfl_xor_sync(0xffffffffu, ks, 2);
                if (l4 == 0) atomicAdd(&g_Ks2[b*Mm + (r - Mm)], ks);
            }
        }
    }
}

// ---------------- kernel: S = Kf . x^T (split-k over n, double-buffered) + gate partials ----------------
#define S_STG (64*36 + 128*36)
#define S_SMEM (2 * S_STG * 4)
__global__ __launch_bounds__(256, 2) void s_mma_kernel(const float* __restrict__ x) {
    extern __shared__ float ssm[];

    const int tid = threadIdx.x;
    const int wid = tid >> 5;
    const int lid = tid & 31;
    const int g4  = lid >> 2;
    const int l4  = lid & 3;
    const int wm  = wid >> 2;          // 0..1
    const int wn  = wid & 3;           // 0..3

    const int b     = blockIdx.z;
    const int c0    = blockIdx.y * 128;
    const int nbase = blockIdx.x * 512;

    const float* kf = g_Kf + (size_t)b * Mm * Nn + nbase;
    const float* xp = x + ((size_t)(b*Cc + c0)) * Nn + nbase;

    float acc[2][4][4];
    #pragma unroll
    for (int mi = 0; mi < 2; mi++)
        #pragma unroll
        for (int ni = 0; ni < 4; ni++)
            #pragma unroll
            for (int q = 0; q < 4; q++) acc[mi][ni][q] = 0.f;

    float gmx[4] = {-INFINITY, -INFINITY, -INFINITY, -INFINITY};
    float gsm[4] = {0.f, 0.f, 0.f, 0.f};

    const int lrow = tid >> 3;
    const int lf   = (tid & 7) * 4;

    // preload chunk 0 into stage 0 (with gate update)
    {
        float* As0 = ssm;
        float* Bs0 = ssm + 64 * 36;
        #pragma unroll
        for (int p = 0; p < 2; p++) {
            int row = lrow + p * 32;
            *(float4*)&As0[row * 36 + lf] = *(const float4*)(kf + (size_t)row * Nn + lf);
        }
        #pragma unroll
        for (int p = 0; p < 4; p++) {
            int row = lrow + p * 32;
            float4 v = *(const float4*)(xp + (size_t)row * Nn + lf);
            gmx[p] = fmaxf(gmx[p], fmaxf(fmaxf(v.x, v.y), fmaxf(v.z, v.w)));
            gsm[p] += (v.x + v.y) + (v.z + v.w);
            *(float4*)&Bs0[row * 36 + lf] = v;
        }
    }
    __syncthreads();

    for (int nc = 0; nc < 512; nc += 32) {
        const int st = (nc >> 5) & 1;
        const float* Asb = ssm + st * S_STG;
        const float* Bsb = Asb + 64 * 36;
        const bool more = (nc + 32 < 512);

        float4 pa[2], pb[4];
        if (more) {
            #pragma unroll
            for (int p = 0; p < 2; p++)
                pa[p] = *(const float4*)(kf + (size_t)(lrow + p*32) * Nn + nc + 32 + lf);
            #pragma unroll
            for (int p = 0; p < 4; p++)
                pb[p] = *(const float4*)(xp + (size_t)(lrow + p*32) * Nn + nc + 32 + lf);
        }

        #pragma unroll
        for (int k8 = 0; k8 < 4; k8++) {
            const int kb = k8 * 8;
            uint32_t afr[2][4];
            #pragma unroll
            for (int mi = 0; mi < 2; mi++) {
                int mr = wm * 32 + mi * 16;
                afr[mi][0] = __float_as_uint(Asb[(mr + g4    ) * 36 + kb + l4]);
                afr[mi][1] = __float_as_uint(Asb[(mr + g4 + 8) * 36 + kb + l4]);
                afr[mi][2] = __float_as_uint(Asb[(mr + g4    ) * 36 + kb + l4 + 4]);
                afr[mi][3] = __float_as_uint(Asb[(mr + g4 + 8) * 36 + kb + l4 + 4]);
            }
            uint32_t bfr[4][2];
            #pragma unroll
            for (int ni = 0; ni < 4; ni++) {
                int nr = wn * 32 + ni * 8 + g4;
                bfr[ni][0] = __float_as_uint(Bsb[nr * 36 + kb + l4]);
                bfr[ni][1] = __float_as_uint(Bsb[nr * 36 + kb + l4 + 4]);
            }
            #pragma unroll
            for (int mi = 0; mi < 2; mi++)
                #pragma unroll
                for (int ni = 0; ni < 4; ni++)
                    mma_tf32(acc[mi][ni], afr[mi], bfr[ni]);
        }

        if (more) {
            float* Asn = ssm + (1 - st) * S_STG;
            float* Bsn = Asn + 64 * 36;
            #pragma unroll
            for (int p = 0; p < 2; p++)
                *(float4*)&Asn[(lrow + p*32) * 36 + lf] = pa[p];
            #pragma unroll
            for (int p = 0; p < 4; p++) {
                float4 v = pb[p];
                gmx[p] = fmaxf(gmx[p], fmaxf(fmaxf(v.x, v.y), fmaxf(v.z, v.w)));
                gsm[p] += (v.x + v.y) + (v.z + v.w);
                *(float4*)&Bsn[(lrow + p*32) * 36 + lf] = v;
            }
        }
        __syncthreads();
    }

    // gate partials: reduce across the 8 lanes sharing each loaded row
    #pragma unroll
    for (int p = 0; p < 4; p++) {
        float mx = gmx[p], sm = gsm[p];
        #pragma unroll
        for (int o = 1; o < 8; o <<= 1) {
            mx = fmaxf(mx, __shfl_xor_sync(0xffffffffu, mx, o));
            sm += __shfl_xor_sync(0xffffffffu, sm, o);
        }
        if ((lid & 7) == 0) {
            int c = c0 + lrow + p * 32;
            atomicMaxF(&g_gmax[b*Cc + c], mx);
            atomicAdd(&g_gsum[b*Cc + c], sm);
        }
    }

    // accumulate S
    #pragma unroll
    for (int mi = 0; mi < 2; mi++) {
        #pragma unroll
        for (int h = 0; h < 2; h++) {
            const int m = wm * 32 + mi * 16 + h * 8 + g4;
            float* srow = g_S + (size_t)(b*Mm + m) * Cc + c0;
            #pragma unroll
            for (int ni = 0; ni < 4; ni++) {
                int c = wn * 32 + ni * 8 + l4 * 2;
                atomicAdd(srow + c,     acc[mi][ni][h*2 + 0]);
                atomicAdd(srow + c + 1, acc[mi][ni][h*2 + 1]);
            }
        }
    }
}

// ---------------- kernel: KVraw += S . Wv^T  (split-k x4, prefetched) ----------------
__global__ __launch_bounds__(256, 2) void kv2_kernel(const float* __restrict__ wv) {
    __shared__ float As[64][36];    // [m][k]
    __shared__ float Bs[64][36];    // [c][k]

    const int tid = threadIdx.x;
    const int wid = tid >> 5;
    const int lid = tid & 31;
    const int g4  = lid >> 2;
    const int l4  = lid & 3;
    const int wm  = wid >> 2;          // 0..1
    const int wn  = wid & 3;           // 0..3

    const int c0 = blockIdx.x * 64;
    const int kh = blockIdx.y * 128;   // k-quarter base
    const int b  = blockIdx.z;

    const float* sp  = g_S + (size_t)b * Mm * Cc + kh;
    const float* wvp = wv + (size_t)c0 * Cc + kh;

    float acc[2][2][4];
    #pragma unroll
    for (int mi = 0; mi < 2; mi++)
        #pragma unroll
        for (int ni = 0; ni < 2; ni++)
            #pragma unroll
            for (int q = 0; q < 4; q++) acc[mi][ni][q] = 0.f;

    const int lrow = tid >> 3;          // 0..31
    const int lf   = (tid & 7) * 4;

    float4 pa[2], pb[2];
    #pragma unroll
    for (int p = 0; p < 2; p++) {
        pa[p] = *(const float4*)(sp  + (size_t)(lrow + p*32) * Cc + lf);
        pb[p] = *(const float4*)(wvp + (size_t)(lrow + p*32) * Cc + lf);
    }

    for (int kc = 0; kc < 128; kc += 32) {
        if (kc) __syncthreads();
        #pragma unroll
        for (int p = 0; p < 2; p++) {
            int row = lrow + p * 32;
            *(float4*)&As[row][lf] = pa[p];
            *(float4*)&Bs[row][lf] = pb[p];
        }
        __syncthreads();
        if (kc + 32 < 128) {
            #pragma unroll
            for (int p = 0; p < 2; p++) {
                pa[p] = *(const float4*)(sp  + (size_t)(lrow + p*32) * Cc + kc + 32 + lf);
                pb[p] = *(const float4*)(wvp + (size_t)(lrow + p*32) * Cc + kc + 32 + lf);
            }
        }
        #pragma unroll
        for (int k8 = 0; k8 < 4; k8++) {
            const int kb = k8 * 8;
            uint32_t afr[2][4];
            #pragma unroll
            for (int mi = 0; mi < 2; mi++) {
                int mr = wm * 32 + mi * 16;
                afr[mi][0] = __float_as_uint(As[mr + g4    ][kb + l4]);
                afr[mi][1] = __float_as_uint(As[mr + g4 + 8][kb + l4]);
                afr[mi][2] = __float_as_uint(As[mr + g4    ][kb + l4 + 4]);
                afr[mi][3] = __float_as_uint(As[mr + g4 + 8][kb + l4 + 4]);
            }
            uint32_t bfr[2][2];
            #pragma unroll
            for (int ni = 0; ni < 2; ni++) {
                int nr = wn * 16 + ni * 8 + g4;
                bfr[ni][0] = __float_as_uint(Bs[nr][kb + l4]);
                bfr[ni][1] = __float_as_uint(Bs[nr][kb + l4 + 4]);
            }
            #pragma unroll
            for (int mi = 0; mi < 2; mi++)
                #pragma unroll
                for (int ni = 0; ni < 2; ni++)
                    mma_tf32(acc[mi][ni], afr[mi], bfr[ni]);
        }
    }

    #pragma unroll
    for (int mi = 0; mi < 2; mi++) {
        #pragma unroll
        for (int h = 0; h < 2; h++) {
            const int m = wm * 32 + mi * 16 + h * 8 + g4;
            float* kvrow = g_KV + (size_t)(b*Mm + m) * Cc;
            #pragma unroll
            for (int ni = 0; ni < 2; ni++) {
                int c = c0 + wn * 16 + ni * 8 + l4 * 2;
                atomicAdd(kvrow + c,     acc[mi][ni][h*2 + 0]);
                atomicAdd(kvrow + c + 1, acc[mi][ni][h*2 + 1]);
            }
        }
    }
}

// ---------------- kernel: out = x + gamma * norm * (KV^T @ Qf), gate/bv folded into load ----------------
#define OSTR_N 136
#define OSTR_C 264
#define OUT_SMEM ((64*OSTR_N + 64*OSTR_C + 64 + 128) * 4)
__global__ __launch_bounds__(512) void out_mma_kernel(const float* __restrict__ x,
                                                      const float* __restrict__ gamma,
                                                      const float* __restrict__ bv,
                                                      float* __restrict__ out) {
    extern __shared__ float osm[];
    float* Qs  = osm;                           // [64][136]
    float* KVs = osm + 64 * OSTR_N;             // [64][264]
    float* ks_s   = osm + 64*OSTR_N + 64*OSTR_C;  // [64]
    float* nrm_s  = ks_s + 64;                    // [128]

    const int tid = threadIdx.x;
    const int wid = tid >> 5;
    const int lid = tid & 31;
    const int g4  = lid >> 2;
    const int l4  = lid & 3;
    const int wm  = wid >> 2;          // 0..3  (c, 64 each)
    const int wn  = wid & 3;           // 0..3  (n, 32 each)

    const int n0 = blockIdx.x * 128;
    const int c0 = blockIdx.y * 256;
    const int b  = blockIdx.z;

    const float* qb  = g_Qf + (size_t)b * Mm * Nn;
    const float* kvb = g_KV + (size_t)b * Mm * Cc;

    #pragma unroll
    for (int p = 0; p < 4; p++) {
        int idx = tid + p * 512;
        int row = idx >> 5;
        int c4  = (idx & 31) * 4;
        *(float4*)&Qs[row * OSTR_N + c4] =
            *(const float4*)(qb + (size_t)row * Nn + n0 + c4);
    }
    // KV load with fused epilogue: KV = gate[c] * (KVraw + Ks2[m]*bv[c])
    #pragma unroll
    for (int p = 0; p < 8; p++) {
        int idx = tid + p * 512;
        int row = idx >> 6;
        int c4  = (idx & 63) * 4;
        const int cg = c0 + c4;
        float4 kv = *(const float4*)(kvb + (size_t)row * Cc + cg);
        float ks  = g_Ks2[b*Mm + row];
        float4 bvv = *(const float4*)(bv + cg);
        float4 gm = *(const float4*)(g_gmax + b*Cc + cg);
        float4 gs = *(const float4*)(g_gsum + b*Cc + cg);
        float4 w;
        w.x = (gm.x + gs.x * (1.f/Nn)) * (kv.x + ks * bvv.x);
        w.y = (gm.y + gs.y * (1.f/Nn)) * (kv.y + ks * bvv.y);
        w.z = (gm.z + gs.z * (1.f/Nn)) * (kv.z + ks * bvv.z);
        w.w = (gm.w + gs.w * (1.f/Nn)) * (kv.w + ks * bvv.w);
        *(float4*)&KVs[row * OSTR_C + c4] = w;
    }
    if (tid < 64) ks_s[tid] = g_Ks2[b*Mm + tid] + EPSc;
    __syncthreads();

    if (tid < 128) {
        float s = 0.f;
        #pragma unroll
        for (int m = 0; m < Mm; m++)
            s = fmaf(Qs[m * OSTR_N + tid], ks_s[m], s);
        nrm_s[tid] = 1.f / s;
    }
    __syncthreads();

    float acc[4][4][4];
    #pragma unroll
    for (int mi = 0; mi < 4; mi++)
        #pragma unroll
        for (int ni = 0; ni < 4; ni++)
            #pragma unroll
            for (int q = 0; q < 4; q++) acc[mi][ni][q] = 0.f;

    #pragma unroll
    for (int k8 = 0; k8 < 8; k8++) {
        const int kb = k8 * 8;
        uint32_t afr[4][4];
        #pragma unroll
        for (int mi = 0; mi < 4; mi++) {
            int cr = wm * 64 + mi * 16;
            afr[mi][0] = __float_as_uint(KVs[(kb + l4    ) * OSTR_C + cr + g4]);
            afr[mi][1] = __float_as_uint(KVs[(kb + l4    ) * OSTR_C + cr + g4 + 8]);
            afr[mi][2] = __float_as_uint(KVs[(kb + l4 + 4) * OSTR_C + cr + g4]);
            afr[mi][3] = __float_as_uint(KVs[(kb + l4 + 4) * OSTR_C + cr + g4 + 8]);
        }
        uint32_t bfr[4][2];
        #pragma unroll
        for (int ni = 0; ni < 4; ni++) {
            int nr = wn * 32 + ni * 8 + g4;
            bfr[ni][0] = __float_as_uint(Qs[(kb + l4    ) * OSTR_N + nr]);
            bfr[ni][1] = __float_as_uint(Qs[(kb + l4 + 4) * OSTR_N + nr]);
        }
        #pragma unroll
        for (int mi = 0; mi < 4; mi++)
            #pragma unroll
            for (int ni = 0; ni < 4; ni++)
                mma_tf32(acc[mi][ni], afr[mi], bfr[ni]);
    }

    const float g = gamma[0];
    float2 nrm[4];
    #pragma unroll
    for (int ni = 0; ni < 4; ni++)
        nrm[ni] = *(float2*)&nrm_s[wn*32 + ni*8 + l4*2];

    #pragma unroll
    for (int mi = 0; mi < 4; mi++) {
        #pragma unroll
        for (int h = 0; h < 2; h++) {
            const int c = c0 + wm * 64 + mi * 16 + h * 8 + g4;
            const size_t off = ((size_t)(b * Cc + c)) * Nn + n0;
            #pragma unroll
            for (int ni = 0; ni < 4; ni++) {
                int ncol = wn * 32 + ni * 8 + l4 * 2;
                float2 xv = *(const float2*)(x + off + ncol);
                float2 r;
                r.x = xv.x + g * nrm[ni].x * acc[mi][ni][h*2 + 0];
                r.y = xv.y + g * nrm[ni].y * acc[mi][ni][h*2 + 1];
                *(float2*)(out + off + ncol) = r;
            }
        }
    }
}

// ---------------- launch (single stream) ----------------
extern "C" void kernel_launch(void* const* d_in, const int* in_sizes, int n_in,
                              void* d_out, int out_size) {
    const float* x     = (const float*)d_in[0];
    const float* wq    = (const float*)d_in[1];
    const float* bq    = (const float*)d_in[2];
    const float* wk    = (const float*)d_in[3];
    const float* bk    = (const float*)d_in[4];
    const float* wv    = (const float*)d_in[5];
    const float* bv    = (const float*)d_in[6];
    const float* gamma = (const float*)d_in[7];
    float* out = (float*)d_out;

    cudaFuncSetAttribute(qk_mma_kernel, cudaFuncAttributeMaxDynamicSharedMemorySize, QK_SMEM);
    cudaFuncSetAttribute(s_mma_kernel, cudaFuncAttributeMaxDynamicSharedMemorySize, S_SMEM);
    cudaFuncSetAttribute(out_mma_kernel, cudaFuncAttributeMaxDynamicSharedMemorySize, OUT_SMEM);

    zero_kernel<<<(Bz*Mm*Cc + 255) / 256, 256>>>();
    qk_mma_kernel<<<dim3(Nn/128, Bz), 256, QK_SMEM>>>(x, wq, bq, wk, bk);
    s_mma_kernel<<<dim3(8, Cc/128, Bz), 256, S_SMEM>>>(x);
    kv2_kernel<<<dim3(Cc/64, 4, Bz), 256>>>(wv);
    out_mma_kernel<<<dim3(Nn/128, Cc/256, Bz), 512, OUT_SMEM>>>(x, gamma, bv, out);
}

// round 16
// speedup vs baseline: 1.3994x; 1.0644x over previous
#include <cuda_runtime.h>
#include <math.h>
#include <stdint.h>

#define Bz   8
#define Cc   512
#define Nn   4096
#define Mm   64
#define EPSc 1e-6f

// ---------------- device scratch ----------------
__device__ uint32_t g_Qh[Bz*Mm*(Nn/2)];  // softplus(Q) packed bf16 pairs along n
__device__ uint32_t g_Kh[Bz*Mm*(Nn/2)];  // softplus(K) packed bf16 pairs along n
__device__ float g_S [Bz*Mm*Cc];   // Kf . x^T     [b][m][c']
__device__ float g_KV[Bz*Mm*Cc];   // RAW S.Wv^T accumulator [b][m][c]
__device__ float g_Ks2[Bz*Mm];     // sum_n Kf
__device__ float g_gmax[Bz*Cc];
__device__ float g_gsum[Bz*Cc];

// ---------------- helpers ----------------
__device__ __forceinline__ void mma_tf32(float* d, const uint32_t* a, const uint32_t* b) {
    asm volatile(
        "mma.sync.aligned.m16n8k8.row.col.f32.tf32.tf32.f32 "
        "{%0,%1,%2,%3}, {%4,%5,%6,%7}, {%8,%9}, {%0,%1,%2,%3};"
        : "+f"(d[0]), "+f"(d[1]), "+f"(d[2]), "+f"(d[3])
        : "r"(a[0]), "r"(a[1]), "r"(a[2]), "r"(a[3]), "r"(b[0]), "r"(b[1]));
}
__device__ __forceinline__ void mma_bf16(float* d, const uint32_t* a, const uint32_t* b) {
    asm volatile(
        "mma.sync.aligned.m16n8k16.row.col.f32.bf16.bf16.f32 "
        "{%0,%1,%2,%3}, {%4,%5,%6,%7}, {%8,%9}, {%0,%1,%2,%3};"
        : "+f"(d[0]), "+f"(d[1]), "+f"(d[2]), "+f"(d[3])
        : "r"(a[0]), "r"(a[1]), "r"(a[2]), "r"(a[3]), "r"(b[0]), "r"(b[1]));
}
// pack two f32 into bf16x2: lo = first (even k), hi = second (odd k)
__device__ __forceinline__ uint32_t pack_bf16(float lo, float hi) {
    uint32_t r;
    asm("cvt.rn.bf16x2.f32 %0, %1, %2;" : "=r"(r) : "f"(hi), "f"(lo));
    return r;
}
__device__ __forceinline__ float bf16_lo(uint32_t w) { return __uint_as_float(w << 16); }
__device__ __forceinline__ float bf16_hi(uint32_t w) { return __uint_as_float(w & 0xFFFF0000u); }
__device__ __forceinline__ void atomicMaxF(float* addr, float v) {
    if (v >= 0.f) atomicMax((int*)addr, __float_as_int(v));
    else          atomicMin((unsigned int*)addr, __float_as_uint(v));
}
__device__ __forceinline__ float softplus_f(float v) {
    return fmaxf(v, 0.f) + __logf(1.f + __expf(-fabsf(v)));
}

// ---------------- kernel: Q,K projection GEMM (bf16, double-buffered) + scratch zeroing ----------------
// D[r][n] = sum_c W[r][c] * x[b][c][n], r in [0,128): rows 0..63 wq, 64..127 wk
#define QK_ASTR 20
#define QK_XSTR 132
#define QK_STG  (128*QK_ASTR + 16*QK_XSTR)
#define QK_SMEM (2 * QK_STG * 4)
__global__ __launch_bounds__(256, 2) void qk_mma_kernel(
    const float* __restrict__ x,
    const float* __restrict__ wq, const float* __restrict__ bq,
    const float* __restrict__ wk, const float* __restrict__ bk)
{
    extern __shared__ uint32_t qsm[];

    const int tid = threadIdx.x;
    const int wid = tid >> 5;
    const int lid = tid & 31;
    const int g4  = lid >> 2;
    const int l4  = lid & 3;
    const int wm  = wid >> 1;          // 0..3 over r
    const int wn  = wid & 1;           // 0..1 over n

    const int n0 = blockIdx.x * 128;
    const int b  = blockIdx.y;

    // ---- scratch zeroing (s/kv2 consume these AFTER this kernel completes) ----
    {
        int gtid = (blockIdx.y * gridDim.x + blockIdx.x) * 256 + tid;   // 0..65535
        float4 z4 = {0.f, 0.f, 0.f, 0.f};
        *(float4*)&g_S [gtid * 4] = z4;
        *(float4*)&g_KV[gtid * 4] = z4;
        if (gtid < Bz*Cc) { g_gmax[gtid] = -INFINITY; g_gsum[gtid] = 0.f; }
        if (gtid < Bz*Mm) g_Ks2[gtid] = 0.f;
    }

    const float* xb = x + (size_t)b * Cc * Nn;

    float acc[2][8][4];
    #pragma unroll
    for (int mi = 0; mi < 2; mi++)
        #pragma unroll
        for (int ni = 0; ni < 8; ni++)
            #pragma unroll
            for (int q = 0; q < 4; q++) acc[mi][ni][q] = 0.f;

    const int lrow = tid >> 3;
    const int lf   = (tid & 7) * 4;

    const float* wsrc[4];
    #pragma unroll
    for (int p = 0; p < 4; p++) {
        int row = lrow + p * 32;
        wsrc[p] = (row < Mm) ? (wq + (size_t)row * Cc) : (wk + (size_t)(row - Mm) * Cc);
    }
    const int bj0 = tid >> 5;
    const int bn4 = (tid & 31) * 4;

    // preload chunk 0 into stage 0
    {
        uint32_t* As0 = qsm;
        uint32_t* Xs0 = qsm + 128 * QK_ASTR;
        #pragma unroll
        for (int p = 0; p < 4; p++) {
            int row = lrow + p * 32;
            float4 va = *(const float4*)(wsrc[p] + lf);
            As0[row * QK_ASTR + (lf >> 1)    ] = pack_bf16(va.x, va.y);
            As0[row * QK_ASTR + (lf >> 1) + 1] = pack_bf16(va.z, va.w);
        }
        #pragma unroll
        for (int p = 0; p < 2; p++) {
            int j = bj0 + p * 8;
            float4 r0 = *(const float4*)(xb + (size_t)(2*j    ) * Nn + n0 + bn4);
            float4 r1 = *(const float4*)(xb + (size_t)(2*j + 1) * Nn + n0 + bn4);
            uint4 w;
            w.x = pack_bf16(r0.x, r1.x);
            w.y = pack_bf16(r0.y, r1.y);
            w.z = pack_bf16(r0.z, r1.z);
            w.w = pack_bf16(r0.w, r1.w);
            *(uint4*)&Xs0[j * QK_XSTR + bn4] = w;
        }
    }
    __syncthreads();

    for (int kc = 0; kc < Cc; kc += 32) {
        const int st = (kc >> 5) & 1;
        const uint32_t* Asb = qsm + st * QK_STG;
        const uint32_t* Xsb = Asb + 128 * QK_ASTR;
        const bool more = (kc + 32 < Cc);

        float4 va[4], r0[2], r1[2];
        if (more) {
            #pragma unroll
            for (int p = 0; p < 4; p++)
                va[p] = *(const float4*)(wsrc[p] + kc + 32 + lf);
            #pragma unroll
            for (int p = 0; p < 2; p++) {
                int j = bj0 + p * 8;
                r0[p] = *(const float4*)(xb + (size_t)(kc + 32 + 2*j    ) * Nn + n0 + bn4);
                r1[p] = *(const float4*)(xb + (size_t)(kc + 32 + 2*j + 1) * Nn + n0 + bn4);
            }
        }

        #pragma unroll
        for (int s16 = 0; s16 < 2; s16++) {
            const int kb2 = s16 * 8;
            uint32_t afr[2][4];
            #pragma unroll
            for (int mi = 0; mi < 2; mi++) {
                int mr = wm * 32 + mi * 16;
                afr[mi][0] = Asb[(mr + g4    ) * QK_ASTR + kb2 + l4];
                afr[mi][1] = Asb[(mr + g4 + 8) * QK_ASTR + kb2 + l4];
                afr[mi][2] = Asb[(mr + g4    ) * QK_ASTR + kb2 + l4 + 4];
                afr[mi][3] = Asb[(mr + g4 + 8) * QK_ASTR + kb2 + l4 + 4];
            }
            uint32_t bfr[8][2];
            #pragma unroll
            for (int ni = 0; ni < 8; ni++) {
                int nr = wn * 64 + ni * 8 + g4;
                bfr[ni][0] = Xsb[(kb2 + l4    ) * QK_XSTR + nr];
                bfr[ni][1] = Xsb[(kb2 + l4 + 4) * QK_XSTR + nr];
            }
            #pragma unroll
            for (int mi = 0; mi < 2; mi++)
                #pragma unroll
                for (int ni = 0; ni < 8; ni++)
                    mma_bf16(acc[mi][ni], afr[mi], bfr[ni]);
        }

        if (more) {
            uint32_t* Asn = qsm + (1 - st) * QK_STG;
            uint32_t* Xsn = Asn + 128 * QK_ASTR;
            #pragma unroll
            for (int p = 0; p < 4; p++) {
                int row = lrow + p * 32;
                Asn[row * QK_ASTR + (lf >> 1)    ] = pack_bf16(va[p].x, va[p].y);
                Asn[row * QK_ASTR + (lf >> 1) + 1] = pack_bf16(va[p].z, va[p].w);
            }
            #pragma unroll
            for (int p = 0; p < 2; p++) {
                int j = bj0 + p * 8;
                uint4 w;
                w.x = pack_bf16(r0[p].x, r1[p].x);
                w.y = pack_bf16(r0[p].y, r1[p].y);
                w.z = pack_bf16(r0[p].z, r1[p].z);
                w.w = pack_bf16(r0[p].w, r1[p].w);
                *(uint4*)&Xsn[j * QK_XSTR + bn4] = w;
            }
        }
        __syncthreads();
    }

    // epilogue: bias + softplus; pack to bf16 pairs; write Qh/Kh
    #pragma unroll
    for (int mi = 0; mi < 2; mi++) {
        #pragma unroll
        for (int h = 0; h < 2; h++) {
            const int r = wm * 32 + mi * 16 + h * 8 + g4;
            float bias; uint32_t* dst;
            if (r < Mm) { bias = bq[r];      dst = g_Qh + (size_t)(b*Mm + r) * (Nn/2); }
            else        { bias = bk[r - Mm]; dst = g_Kh + (size_t)(b*Mm + r - Mm) * (Nn/2); }
            #pragma unroll
            for (int ni = 0; ni < 8; ni++) {
                float v0 = softplus_f(acc[mi][ni][h*2 + 0] + bias);
                float v1 = softplus_f(acc[mi][ni][h*2 + 1] + bias);
                dst[n0/2 + wn * 32 + ni * 4 + l4] = pack_bf16(v0, v1);
            }
        }
    }
}

// ---------------- kernel: S = Kf . x^T (bf16, split-k over n, double-buffered) + gate + Ks2 ----------------
#define S_ASTR 20
#define S_STG (64*S_ASTR + 128*S_ASTR)
#define S_SMEM (2 * S_STG * 4)
__global__ __launch_bounds__(256, 2) void s_mma_kernel(const float* __restrict__ x) {
    extern __shared__ uint32_t ssm[];

    const int tid = threadIdx.x;
    const int wid = tid >> 5;
    const int lid = tid & 31;
    const int g4  = lid >> 2;
    const int l4  = lid & 3;
    const int wm  = wid >> 2;          // 0..1 (m)
    const int wn  = wid & 3;           // 0..3 (c')

    const int b     = blockIdx.z;
    const int c0    = blockIdx.y * 128;
    const int nbase = blockIdx.x * 512;
    const bool do_ks = (blockIdx.y == 0);

    const uint32_t* kh = g_Kh + (size_t)b * Mm * (Nn/2) + nbase/2;
    const float* xp = x + ((size_t)(b*Cc + c0)) * Nn + nbase;

    float acc[2][4][4];
    #pragma unroll
    for (int mi = 0; mi < 2; mi++)
        #pragma unroll
        for (int ni = 0; ni < 4; ni++)
            #pragma unroll
            for (int q = 0; q < 4; q++) acc[mi][ni][q] = 0.f;

    // A loader: row = tid>>2 (0..63), word4 = (tid&3)*4 ; one uint4 (16 bf16) per chunk
    const int arow = tid >> 2;
    const int aw4  = (tid & 3) * 4;
    // B loader: task = tid + p*256 (p<2): row = task>>2 (0..127), fo = (task&3)*8 floats
    const int brow0 = tid >> 2;         // p=0 row; p=1 row = brow0+64
    const int bfo   = (tid & 3) * 8;

    float ksum = 0.f;
    float gmx[2] = {-INFINITY, -INFINITY};
    float gsm[2] = {0.f, 0.f};

    // preload chunk 0 into stage 0
    {
        uint32_t* As0 = ssm;
        uint32_t* Bs0 = ssm + 64 * S_ASTR;
        uint4 a4 = *(const uint4*)(kh + (size_t)arow * (Nn/2) + aw4);
        *(uint4*)&As0[arow * S_ASTR + aw4] = a4;
        if (do_ks) {
            ksum += bf16_lo(a4.x) + bf16_hi(a4.x) + bf16_lo(a4.y) + bf16_hi(a4.y)
                  + bf16_lo(a4.z) + bf16_hi(a4.z) + bf16_lo(a4.w) + bf16_hi(a4.w);
        }
        #pragma unroll
        for (int p = 0; p < 2; p++) {
            int row = brow0 + p * 64;
            float4 v0 = *(const float4*)(xp + (size_t)row * Nn + bfo);
            float4 v1 = *(const float4*)(xp + (size_t)row * Nn + bfo + 4);
            gmx[p] = fmaxf(gmx[p], fmaxf(fmaxf(fmaxf(v0.x, v0.y), fmaxf(v0.z, v0.w)),
                                         fmaxf(fmaxf(v1.x, v1.y), fmaxf(v1.z, v1.w))));
            gsm[p] += (v0.x + v0.y) + (v0.z + v0.w) + (v1.x + v1.y) + (v1.z + v1.w);
            uint4 w;
            w.x = pack_bf16(v0.x, v0.y);
            w.y = pack_bf16(v0.z, v0.w);
            w.z = pack_bf16(v1.x, v1.y);
            w.w = pack_bf16(v1.z, v1.w);
            *(uint4*)&Bs0[row * S_ASTR + (bfo >> 1)] = w;
        }
    }
    __syncthreads();

    for (int nc = 0; nc < 512; nc += 32) {
        const int st = (nc >> 5) & 1;
        const uint32_t* Asb = ssm + st * S_STG;
        const uint32_t* Bsb = Asb + 64 * S_ASTR;
        const bool more = (nc + 32 < 512);

        uint4 a4;
        float4 v0[2], v1[2];
        if (more) {
            a4 = *(const uint4*)(kh + (size_t)arow * (Nn/2) + (nc + 32)/2 + aw4);
            #pragma unroll
            for (int p = 0; p < 2; p++) {
                int row = brow0 + p * 64;
                v0[p] = *(const float4*)(xp + (size_t)row * Nn + nc + 32 + bfo);
                v1[p] = *(const float4*)(xp + (size_t)row * Nn + nc + 32 + bfo + 4);
            }
        }

        #pragma unroll
        for (int s16 = 0; s16 < 2; s16++) {
            const int kb2 = s16 * 8;
            uint32_t afr[2][4];
            #pragma unroll
            for (int mi = 0; mi < 2; mi++) {
                int mr = wm * 32 + mi * 16;
                afr[mi][0] = Asb[(mr + g4    ) * S_ASTR + kb2 + l4];
                afr[mi][1] = Asb[(mr + g4 + 8) * S_ASTR + kb2 + l4];
                afr[mi][2] = Asb[(mr + g4    ) * S_ASTR + kb2 + l4 + 4];
                afr[mi][3] = Asb[(mr + g4 + 8) * S_ASTR + kb2 + l4 + 4];
            }
            uint32_t bfr[4][2];
            #pragma unroll
            for (int ni = 0; ni < 4; ni++) {
                int nr = wn * 32 + ni * 8 + g4;
                bfr[ni][0] = Bsb[nr * S_ASTR + kb2 + l4];
                bfr[ni][1] = Bsb[nr * S_ASTR + kb2 + l4 + 4];
            }
            #pragma unroll
            for (int mi = 0; mi < 2; mi++)
                #pragma unroll
                for (int ni = 0; ni < 4; ni++)
                    mma_bf16(acc[mi][ni], afr[mi], bfr[ni]);
        }

        if (more) {
            uint32_t* Asn = ssm + (1 - st) * S_STG;
            uint32_t* Bsn = Asn + 64 * S_ASTR;
            *(uint4*)&Asn[arow * S_ASTR + aw4] = a4;
            if (do_ks) {
                ksum += bf16_lo(a4.x) + bf16_hi(a4.x) + bf16_lo(a4.y) + bf16_hi(a4.y)
                      + bf16_lo(a4.z) + bf16_hi(a4.z) + bf16_lo(a4.w) + bf16_hi(a4.w);
            }
            #pragma unroll
            for (int p = 0; p < 2; p++) {
                int row = brow0 + p * 64;
                gmx[p] = fmaxf(gmx[p], fmaxf(fmaxf(fmaxf(v0[p].x, v0[p].y), fmaxf(v0[p].z, v0[p].w)),
                                             fmaxf(fmaxf(v1[p].x, v1[p].y), fmaxf(v1[p].z, v1[p].w))));
                gsm[p] += (v0[p].x + v0[p].y) + (v0[p].z + v0[p].w)
                        + (v1[p].x + v1[p].y) + (v1[p].z + v1[p].w);
                uint4 w;
                w.x = pack_bf16(v0[p].x, v0[p].y);
                w.y = pack_bf16(v0[p].z, v0[p].w);
                w.z = pack_bf16(v1[p].x, v1[p].y);
                w.w = pack_bf16(v1[p].z, v1[p].w);
                *(uint4*)&Bsn[row * S_ASTR + (bfo >> 1)] = w;
            }
        }
        __syncthreads();
    }

    // Ks2 partial (only c-tile 0 CTAs): reduce across 4 lanes sharing arow
    if (do_ks) {
        ksum += __shfl_xor_sync(0xffffffffu, ksum, 1);
        ksum += __shfl_xor_sync(0xffffffffu, ksum, 2);
        if ((tid & 3) == 0) atomicAdd(&g_Ks2[b*Mm + arow], ksum);
    }

    // gate partials: reduce across the 4 lanes sharing each loaded row
    #pragma unroll
    for (int p = 0; p < 2; p++) {
        float mx = gmx[p], sm = gsm[p];
        mx = fmaxf(mx, __shfl_xor_sync(0xffffffffu, mx, 1));
        sm += __shfl_xor_sync(0xffffffffu, sm, 1);
        mx = fmaxf(mx, __shfl_xor_sync(0xffffffffu, mx, 2));
        sm += __shfl_xor_sync(0xffffffffu, sm, 2);
        if ((tid & 3) == 0) {
            int c = c0 + brow0 + p * 64;
            atomicMaxF(&g_gmax[b*Cc + c], mx);
            atomicAdd(&g_gsum[b*Cc + c], sm);
        }
    }

    // accumulate S
    #pragma unroll
    for (int mi = 0; mi < 2; mi++) {
        #pragma unroll
        for (int h = 0; h < 2; h++) {
            const int m = wm * 32 + mi * 16 + h * 8 + g4;
            float* srow = g_S + (size_t)(b*Mm + m) * Cc + c0;
            #pragma unroll
            for (int ni = 0; ni < 4; ni++) {
                int c = wn * 32 + ni * 8 + l4 * 2;
                atomicAdd(srow + c,     acc[mi][ni][h*2 + 0]);
                atomicAdd(srow + c + 1, acc[mi][ni][h*2 + 1]);
            }
        }
    }
}

// ---------------- kernel: KVraw += S . Wv^T  (split-k x4, prefetched) ----------------
__global__ __launch_bounds__(256, 2) void kv2_kernel(const float* __restrict__ wv) {
    __shared__ float As[64][36];    // [m][k]
    __shared__ float Bs[64][36];    // [c][k]

    const int tid = threadIdx.x;
    const int wid = tid >> 5;
    const int lid = tid & 31;
    const int g4  = lid >> 2;
    const int l4  = lid & 3;
    const int wm  = wid >> 2;          // 0..1
    const int wn  = wid & 3;           // 0..3

    const int c0 = blockIdx.x * 64;
    const int kh = blockIdx.y * 128;   // k-quarter base
    const int b  = blockIdx.z;

    const float* sp  = g_S + (size_t)b * Mm * Cc + kh;
    const float* wvp = wv + (size_t)c0 * Cc + kh;

    float acc[2][2][4];
    #pragma unroll
    for (int mi = 0; mi < 2; mi++)
        #pragma unroll
        for (int ni = 0; ni < 2; ni++)
            #pragma unroll
            for (int q = 0; q < 4; q++) acc[mi][ni][q] = 0.f;

    const int lrow = tid >> 3;
    const int lf   = (tid & 7) * 4;

    float4 pa[2], pb[2];
    #pragma unroll
    for (int p = 0; p < 2; p++) {
        pa[p] = *(const float4*)(sp  + (size_t)(lrow + p*32) * Cc + lf);
        pb[p] = *(const float4*)(wvp + (size_t)(lrow + p*32) * Cc + lf);
    }

    for (int kc = 0; kc < 128; kc += 32) {
        if (kc) __syncthreads();
        #pragma unroll
        for (int p = 0; p < 2; p++) {
            int row = lrow + p * 32;
            *(float4*)&As[row][lf] = pa[p];
            *(float4*)&Bs[row][lf] = pb[p];
        }
        __syncthreads();
        if (kc + 32 < 128) {
            #pragma unroll
            for (int p = 0; p < 2; p++) {
                pa[p] = *(const float4*)(sp  + (size_t)(lrow + p*32) * Cc + kc + 32 + lf);
                pb[p] = *(const float4*)(wvp + (size_t)(lrow + p*32) * Cc + kc + 32 + lf);
            }
        }
        #pragma unroll
        for (int k8 = 0; k8 < 4; k8++) {
            const int kb = k8 * 8;
            uint32_t afr[2][4];
            #pragma unroll
            for (int mi = 0; mi < 2; mi++) {
                int mr = wm * 32 + mi * 16;
                afr[mi][0] = __float_as_uint(As[mr + g4    ][kb + l4]);
                afr[mi][1] = __float_as_uint(As[mr + g4 + 8][kb + l4]);
                afr[mi][2] = __float_as_uint(As[mr + g4    ][kb + l4 + 4]);
                afr[mi][3] = __float_as_uint(As[mr + g4 + 8][kb + l4 + 4]);
            }
            uint32_t bfr[2][2];
            #pragma unroll
            for (int ni = 0; ni < 2; ni++) {
                int nr = wn * 16 + ni * 8 + g4;
                bfr[ni][0] = __float_as_uint(Bs[nr][kb + l4]);
                bfr[ni][1] = __float_as_uint(Bs[nr][kb + l4 + 4]);
            }
            #pragma unroll
            for (int mi = 0; mi < 2; mi++)
                #pragma unroll
                for (int ni = 0; ni < 2; ni++)
                    mma_tf32(acc[mi][ni], afr[mi], bfr[ni]);
        }
    }

    #pragma unroll
    for (int mi = 0; mi < 2; mi++) {
        #pragma unroll
        for (int h = 0; h < 2; h++) {
            const int m = wm * 32 + mi * 16 + h * 8 + g4;
            float* kvrow = g_KV + (size_t)(b*Mm + m) * Cc;
            #pragma unroll
            for (int ni = 0; ni < 2; ni++) {
                int c = c0 + wn * 16 + ni * 8 + l4 * 2;
                atomicAdd(kvrow + c,     acc[mi][ni][h*2 + 0]);
                atomicAdd(kvrow + c + 1, acc[mi][ni][h*2 + 1]);
            }
        }
    }
}

// ---------------- kernel: out = x + gamma * norm * (KV^T @ Qf), gate/bv folded into load ----------------
#define OSTR_N 136
#define OSTR_C 264
#define OUT_SMEM ((64*OSTR_N + 64*OSTR_C + 64 + 128) * 4)
__global__ __launch_bounds__(512) void out_mma_kernel(const float* __restrict__ x,
                                                      const float* __restrict__ gamma,
                                                      const float* __restrict__ bv,
                                                      float* __restrict__ out) {
    extern __shared__ float osm[];
    float* Qs  = osm;                           // [64][136] f32 (unpacked)
    float* KVs = osm + 64 * OSTR_N;             // [64][264]
    float* ks_s   = osm + 64*OSTR_N + 64*OSTR_C;  // [64]
    float* nrm_s  = ks_s + 64;                    // [128]

    const int tid = threadIdx.x;
    const int wid = tid >> 5;
    const int lid = tid & 31;
    const int g4  = lid >> 2;
    const int l4  = lid & 3;
    const int wm  = wid >> 2;          // 0..3  (c, 64 each)
    const int wn  = wid & 3;           // 0..3  (n, 32 each)

    const int n0 = blockIdx.x * 128;
    const int c0 = blockIdx.y * 256;
    const int b  = blockIdx.z;

    const uint32_t* qb = g_Qh + (size_t)b * Mm * (Nn/2) + n0/2;
    const float* kvb = g_KV + (size_t)b * Mm * Cc;

    // Q load: packed bf16 -> f32 smem. 64 rows x 64 words; uint4 per task (8 n).
    #pragma unroll
    for (int p = 0; p < 2; p++) {
        int t = tid + p * 512;
        int row = t >> 4;
        int w4  = (t & 15) * 4;
        uint4 pk = *(const uint4*)(qb + (size_t)row * (Nn/2) + w4);
        float* dst = &Qs[row * OSTR_N + w4 * 2];
        float4 f0 = { bf16_lo(pk.x), bf16_hi(pk.x), bf16_lo(pk.y), bf16_hi(pk.y) };
        float4 f1 = { bf16_lo(pk.z), bf16_hi(pk.z), bf16_lo(pk.w), bf16_hi(pk.w) };
        *(float4*)(dst)     = f0;
        *(float4*)(dst + 4) = f1;
    }
    // KV load with fused epilogue: KV = gate[c] * (KVraw + Ks2[m]*bv[c])
    #pragma unroll
    for (int p = 0; p < 8; p++) {
        int idx = tid + p * 512;
        int row = idx >> 6;
        int c4  = (idx & 63) * 4;
        const int cg = c0 + c4;
        float4 kv = *(const float4*)(kvb + (size_t)row * Cc + cg);
        float ks  = g_Ks2[b*Mm + row];
        float4 bvv = *(const float4*)(bv + cg);
        float4 gm = *(const float4*)(g_gmax + b*Cc + cg);
        float4 gs = *(const float4*)(g_gsum + b*Cc + cg);
        float4 w;
        w.x = (gm.x + gs.x * (1.f/Nn)) * (kv.x + ks * bvv.x);
        w.y = (gm.y + gs.y * (1.f/Nn)) * (kv.y + ks * bvv.y);
        w.z = (gm.z + gs.z * (1.f/Nn)) * (kv.z + ks * bvv.z);
        w.w = (gm.w + gs.w * (1.f/Nn)) * (kv.w + ks * bvv.w);
        *(float4*)&KVs[row * OSTR_C + c4] = w;
    }
    if (tid < 64) ks_s[tid] = g_Ks2[b*Mm + tid] + EPSc;
    __syncthreads();

    if (tid < 128) {
        float s = 0.f;
        #pragma unroll
        for (int m = 0; m < Mm; m++)
            s = fmaf(Qs[m * OSTR_N + tid], ks_s[m], s);
        nrm_s[tid] = 1.f / s;
    }
    __syncthreads();

    float acc[4][4][4];
    #pragma unroll
    for (int mi = 0; mi < 4; mi++)
        #pragma unroll
        for (int ni = 0; ni < 4; ni++)
            #pragma unroll
            for (int q = 0; q < 4; q++) acc[mi][ni][q] = 0.f;

    #pragma unroll
    for (int k8 = 0; k8 < 8; k8++) {
        const int kb = k8 * 8;
        uint32_t afr[4][4];
        #pragma unroll
        for (int mi = 0; mi < 4; mi++) {
            int cr = wm * 64 + mi * 16;
            afr[mi][0] = __float_as_uint(KVs[(kb + l4    ) * OSTR_C + cr + g4]);
            afr[mi][1] = __float_as_uint(KVs[(kb + l4    ) * OSTR_C + cr + g4 + 8]);
            afr[mi][2] = __float_as_uint(KVs[(kb + l4 + 4) * OSTR_C + cr + g4]);
            afr[mi][3] = __float_as_uint(KVs[(kb + l4 + 4) * OSTR_C + cr + g4 + 8]);
        }
        uint32_t bfr[4][2];
        #pragma unroll
        for (int ni = 0; ni < 4; ni++) {
            int nr = wn * 32 + ni * 8 + g4;
            bfr[ni][0] = __float_as_uint(Qs[(kb + l4    ) * OSTR_N + nr]);
            bfr[ni][1] = __float_as_uint(Qs[(kb + l4 + 4) * OSTR_N + nr]);
        }
        #pragma unroll
        for (int mi = 0; mi < 4; mi++)
            #pragma unroll
            for (int ni = 0; ni < 4; ni++)
                mma_tf32(acc[mi][ni], afr[mi], bfr[ni]);
    }

    const float g = gamma[0];
    float2 nrm[4];
    #pragma unroll
    for (int ni = 0; ni < 4; ni++)
        nrm[ni] = *(float2*)&nrm_s[wn*32 + ni*8 + l4*2];

    #pragma unroll
    for (int mi = 0; mi < 4; mi++) {
        #pragma unroll
        for (int h = 0; h < 2; h++) {
            const int c = c0 + wm * 64 + mi * 16 + h * 8 + g4;
            const size_t off = ((size_t)(b * Cc + c)) * Nn + n0;
            #pragma unroll
            for (int ni = 0; ni < 4; ni++) {
                int ncol = wn * 32 + ni * 8 + l4 * 2;
                float2 xv = *(const float2*)(x + off + ncol);
                float2 r;
                r.x = xv.x + g * nrm[ni].x * acc[mi][ni][h*2 + 0];
                r.y = xv.y + g * nrm[ni].y * acc[mi][ni][h*2 + 1];
                *(float2*)(out + off + ncol) = r;
            }
        }
    }
}

// ---------------- launch (single stream, 4 kernels) ----------------
extern "C" void kernel_launch(void* const* d_in, const int* in_sizes, int n_in,
                              void* d_out, int out_size) {
    const float* x     = (const float*)d_in[0];
    const float* wq    = (const float*)d_in[1];
    const float* bq    = (const float*)d_in[2];
    const float* wk    = (const float*)d_in[3];
    const float* bk    = (const float*)d_in[4];
    const float* wv    = (const float*)d_in[5];
    const float* bv    = (const float*)d_in[6];
    const float* gamma = (const float*)d_in[7];
    float* out = (float*)d_out;

    cudaFuncSetAttribute(qk_mma_kernel, cudaFuncAttributeMaxDynamicSharedMemorySize, QK_SMEM);
    cudaFuncSetAttribute(s_mma_kernel, cudaFuncAttributeMaxDynamicSharedMemorySize, S_SMEM);
    cudaFuncSetAttribute(out_mma_kernel, cudaFuncAttributeMaxDynamicSharedMemorySize, OUT_SMEM);

    qk_mma_kernel<<<dim3(Nn/128, Bz), 256, QK_SMEM>>>(x, wq, bq, wk, bk);
    s_mma_kernel<<<dim3(8, Cc/128, Bz), 256, S_SMEM>>>(x);
    kv2_kernel<<<dim3(Cc/64, 4, Bz), 256>>>(wv);
    out_mma_kernel<<<dim3(Nn/128, Cc/256, Bz), 512, OUT_SMEM>>>(x, gamma, bv, out);
}

// round 17
// speedup vs baseline: 1.4792x; 1.0570x over previous
#include <cuda_runtime.h>
#include <math.h>
#include <stdint.h>

#define Bz   8
#define Cc   512
#define Nn   4096
#define Mm   64
#define EPSc 1e-6f

// ---------------- device scratch ----------------
__device__ uint32_t g_Qh[Bz*Mm*(Nn/2)];  // softplus(Q) packed bf16 pairs along n
__device__ uint32_t g_Kh[Bz*Mm*(Nn/2)];  // softplus(K) packed bf16 pairs along n
__device__ float g_S [Bz*Mm*Cc];   // Kf . x^T     [b][m][c']
__device__ float g_KV[Bz*Mm*Cc];   // RAW S.Wv^T accumulator [b][m][c]
__device__ float g_Ks2[Bz*Mm];     // sum_n Kf
__device__ float g_gmax[Bz*Cc];
__device__ float g_gsum[Bz*Cc];

// ---------------- helpers ----------------
__device__ __forceinline__ void mma_tf32(float* d, const uint32_t* a, const uint32_t* b) {
    asm volatile(
        "mma.sync.aligned.m16n8k8.row.col.f32.tf32.tf32.f32 "
        "{%0,%1,%2,%3}, {%4,%5,%6,%7}, {%8,%9}, {%0,%1,%2,%3};"
        : "+f"(d[0]), "+f"(d[1]), "+f"(d[2]), "+f"(d[3])
        : "r"(a[0]), "r"(a[1]), "r"(a[2]), "r"(a[3]), "r"(b[0]), "r"(b[1]));
}
__device__ __forceinline__ void mma_bf16(float* d, const uint32_t* a, const uint32_t* b) {
    asm volatile(
        "mma.sync.aligned.m16n8k16.row.col.f32.bf16.bf16.f32 "
        "{%0,%1,%2,%3}, {%4,%5,%6,%7}, {%8,%9}, {%0,%1,%2,%3};"
        : "+f"(d[0]), "+f"(d[1]), "+f"(d[2]), "+f"(d[3])
        : "r"(a[0]), "r"(a[1]), "r"(a[2]), "r"(a[3]), "r"(b[0]), "r"(b[1]));
}
// pack two f32 into bf16x2: lo = first (even k), hi = second (odd k)
__device__ __forceinline__ uint32_t pack_bf16(float lo, float hi) {
    uint32_t r;
    asm("cvt.rn.bf16x2.f32 %0, %1, %2;" : "=r"(r) : "f"(hi), "f"(lo));
    return r;
}
__device__ __forceinline__ float bf16_lo(uint32_t w) { return __uint_as_float(w << 16); }
__device__ __forceinline__ float bf16_hi(uint32_t w) { return __uint_as_float(w & 0xFFFF0000u); }
__device__ __forceinline__ void atomicMaxF(float* addr, float v) {
    if (v >= 0.f) atomicMax((int*)addr, __float_as_int(v));
    else          atomicMin((unsigned int*)addr, __float_as_uint(v));
}
__device__ __forceinline__ float softplus_f(float v) {
    return fmaxf(v, 0.f) + __logf(1.f + __expf(-fabsf(v)));
}

// ---------------- kernel: Q,K projection GEMM (bf16, double-buffered) + scratch zeroing ----------------
#define QK_ASTR 20
#define QK_XSTR 132
#define QK_STG  (128*QK_ASTR + 16*QK_XSTR)
#define QK_SMEM (2 * QK_STG * 4)
__global__ __launch_bounds__(256, 2) void qk_mma_kernel(
    const float* __restrict__ x,
    const float* __restrict__ wq, const float* __restrict__ bq,
    const float* __restrict__ wk, const float* __restrict__ bk)
{
    extern __shared__ uint32_t qsm[];

    const int tid = threadIdx.x;
    const int wid = tid >> 5;
    const int lid = tid & 31;
    const int g4  = lid >> 2;
    const int l4  = lid & 3;
    const int wm  = wid >> 1;
    const int wn  = wid & 1;

    const int n0 = blockIdx.x * 128;
    const int b  = blockIdx.y;

    // ---- scratch zeroing ----
    {
        int gtid = (blockIdx.y * gridDim.x + blockIdx.x) * 256 + tid;
        float4 z4 = {0.f, 0.f, 0.f, 0.f};
        *(float4*)&g_S [gtid * 4] = z4;
        *(float4*)&g_KV[gtid * 4] = z4;
        if (gtid < Bz*Cc) { g_gmax[gtid] = -INFINITY; g_gsum[gtid] = 0.f; }
        if (gtid < Bz*Mm) g_Ks2[gtid] = 0.f;
    }

    const float* xb = x + (size_t)b * Cc * Nn;

    float acc[2][8][4];
    #pragma unroll
    for (int mi = 0; mi < 2; mi++)
        #pragma unroll
        for (int ni = 0; ni < 8; ni++)
            #pragma unroll
            for (int q = 0; q < 4; q++) acc[mi][ni][q] = 0.f;

    const int lrow = tid >> 3;
    const int lf   = (tid & 7) * 4;

    const float* wsrc[4];
    #pragma unroll
    for (int p = 0; p < 4; p++) {
        int row = lrow + p * 32;
        wsrc[p] = (row < Mm) ? (wq + (size_t)row * Cc) : (wk + (size_t)(row - Mm) * Cc);
    }
    const int bj0 = tid >> 5;
    const int bn4 = (tid & 31) * 4;

    {
        uint32_t* As0 = qsm;
        uint32_t* Xs0 = qsm + 128 * QK_ASTR;
        #pragma unroll
        for (int p = 0; p < 4; p++) {
            int row = lrow + p * 32;
            float4 va = *(const float4*)(wsrc[p] + lf);
            As0[row * QK_ASTR + (lf >> 1)    ] = pack_bf16(va.x, va.y);
            As0[row * QK_ASTR + (lf >> 1) + 1] = pack_bf16(va.z, va.w);
        }
        #pragma unroll
        for (int p = 0; p < 2; p++) {
            int j = bj0 + p * 8;
            float4 r0 = *(const float4*)(xb + (size_t)(2*j    ) * Nn + n0 + bn4);
            float4 r1 = *(const float4*)(xb + (size_t)(2*j + 1) * Nn + n0 + bn4);
            uint4 w;
            w.x = pack_bf16(r0.x, r1.x);
            w.y = pack_bf16(r0.y, r1.y);
            w.z = pack_bf16(r0.z, r1.z);
            w.w = pack_bf16(r0.w, r1.w);
            *(uint4*)&Xs0[j * QK_XSTR + bn4] = w;
        }
    }
    __syncthreads();

    for (int kc = 0; kc < Cc; kc += 32) {
        const int st = (kc >> 5) & 1;
        const uint32_t* Asb = qsm + st * QK_STG;
        const uint32_t* Xsb = Asb + 128 * QK_ASTR;
        const bool more = (kc + 32 < Cc);

        float4 va[4], r0[2], r1[2];
        if (more) {
            #pragma unroll
            for (int p = 0; p < 4; p++)
                va[p] = *(const float4*)(wsrc[p] + kc + 32 + lf);
            #pragma unroll
            for (int p = 0; p < 2; p++) {
                int j = bj0 + p * 8;
                r0[p] = *(const float4*)(xb + (size_t)(kc + 32 + 2*j    ) * Nn + n0 + bn4);
                r1[p] = *(const float4*)(xb + (size_t)(kc + 32 + 2*j + 1) * Nn + n0 + bn4);
            }
        }

        #pragma unroll
        for (int s16 = 0; s16 < 2; s16++) {
            const int kb2 = s16 * 8;
            uint32_t afr[2][4];
            #pragma unroll
            for (int mi = 0; mi < 2; mi++) {
                int mr = wm * 32 + mi * 16;
                afr[mi][0] = Asb[(mr + g4    ) * QK_ASTR + kb2 + l4];
                afr[mi][1] = Asb[(mr + g4 + 8) * QK_ASTR + kb2 + l4];
                afr[mi][2] = Asb[(mr + g4    ) * QK_ASTR + kb2 + l4 + 4];
                afr[mi][3] = Asb[(mr + g4 + 8) * QK_ASTR + kb2 + l4 + 4];
            }
            uint32_t bfr[8][2];
            #pragma unroll
            for (int ni = 0; ni < 8; ni++) {
                int nr = wn * 64 + ni * 8 + g4;
                bfr[ni][0] = Xsb[(kb2 + l4    ) * QK_XSTR + nr];
                bfr[ni][1] = Xsb[(kb2 + l4 + 4) * QK_XSTR + nr];
            }
            #pragma unroll
            for (int mi = 0; mi < 2; mi++)
                #pragma unroll
                for (int ni = 0; ni < 8; ni++)
                    mma_bf16(acc[mi][ni], afr[mi], bfr[ni]);
        }

        if (more) {
            uint32_t* Asn = qsm + (1 - st) * QK_STG;
            uint32_t* Xsn = Asn + 128 * QK_ASTR;
            #pragma unroll
            for (int p = 0; p < 4; p++) {
                int row = lrow + p * 32;
                Asn[row * QK_ASTR + (lf >> 1)    ] = pack_bf16(va[p].x, va[p].y);
                Asn[row * QK_ASTR + (lf >> 1) + 1] = pack_bf16(va[p].z, va[p].w);
            }
            #pragma unroll
            for (int p = 0; p < 2; p++) {
                int j = bj0 + p * 8;
                uint4 w;
                w.x = pack_bf16(r0[p].x, r1[p].x);
                w.y = pack_bf16(r0[p].y, r1[p].y);
                w.z = pack_bf16(r0[p].z, r1[p].z);
                w.w = pack_bf16(r0[p].w, r1[p].w);
                *(uint4*)&Xsn[j * QK_XSTR + bn4] = w;
            }
        }
        __syncthreads();
    }

    // epilogue: bias + softplus; pack to bf16 pairs; write Qh/Kh
    #pragma unroll
    for (int mi = 0; mi < 2; mi++) {
        #pragma unroll
        for (int h = 0; h < 2; h++) {
            const int r = wm * 32 + mi * 16 + h * 8 + g4;
            float bias; uint32_t* dst;
            if (r < Mm) { bias = bq[r];      dst = g_Qh + (size_t)(b*Mm + r) * (Nn/2); }
            else        { bias = bk[r - Mm]; dst = g_Kh + (size_t)(b*Mm + r - Mm) * (Nn/2); }
            #pragma unroll
            for (int ni = 0; ni < 8; ni++) {
                float v0 = softplus_f(acc[mi][ni][h*2 + 0] + bias);
                float v1 = softplus_f(acc[mi][ni][h*2 + 1] + bias);
                dst[n0/2 + wn * 32 + ni * 4 + l4] = pack_bf16(v0, v1);
            }
        }
    }
}

// ---------------- kernel: S = Kf . x^T (bf16, split-k over n, double-buffered) + gate + Ks2 ----------------
#define S_ASTR 20
#define S_STG (64*S_ASTR + 128*S_ASTR)
#define S_SMEM (2 * S_STG * 4)
__global__ __launch_bounds__(256, 2) void s_mma_kernel(const float* __restrict__ x) {
    extern __shared__ uint32_t ssm[];

    const int tid = threadIdx.x;
    const int wid = tid >> 5;
    const int lid = tid & 31;
    const int g4  = lid >> 2;
    const int l4  = lid & 3;
    const int wm  = wid >> 2;
    const int wn  = wid & 3;

    const int b     = blockIdx.z;
    const int c0    = blockIdx.y * 128;
    const int nbase = blockIdx.x * 512;
    const bool do_ks = (blockIdx.y == 0);

    const uint32_t* kh = g_Kh + (size_t)b * Mm * (Nn/2) + nbase/2;
    const float* xp = x + ((size_t)(b*Cc + c0)) * Nn + nbase;

    float acc[2][4][4];
    #pragma unroll
    for (int mi = 0; mi < 2; mi++)
        #pragma unroll
        for (int ni = 0; ni < 4; ni++)
            #pragma unroll
            for (int q = 0; q < 4; q++) acc[mi][ni][q] = 0.f;

    const int arow = tid >> 2;
    const int aw4  = (tid & 3) * 4;
    const int brow0 = tid >> 2;
    const int bfo   = (tid & 3) * 8;

    float ksum = 0.f;
    float gmx[2] = {-INFINITY, -INFINITY};
    float gsm[2] = {0.f, 0.f};

    {
        uint32_t* As0 = ssm;
        uint32_t* Bs0 = ssm + 64 * S_ASTR;
        uint4 a4 = *(const uint4*)(kh + (size_t)arow * (Nn/2) + aw4);
        *(uint4*)&As0[arow * S_ASTR + aw4] = a4;
        if (do_ks) {
            ksum += bf16_lo(a4.x) + bf16_hi(a4.x) + bf16_lo(a4.y) + bf16_hi(a4.y)
                  + bf16_lo(a4.z) + bf16_hi(a4.z) + bf16_lo(a4.w) + bf16_hi(a4.w);
        }
        #pragma unroll
        for (int p = 0; p < 2; p++) {
            int row = brow0 + p * 64;
            float4 v0 = *(const float4*)(xp + (size_t)row * Nn + bfo);
            float4 v1 = *(const float4*)(xp + (size_t)row * Nn + bfo + 4);
            gmx[p] = fmaxf(gmx[p], fmaxf(fmaxf(fmaxf(v0.x, v0.y), fmaxf(v0.z, v0.w)),
                                         fmaxf(fmaxf(v1.x, v1.y), fmaxf(v1.z, v1.w))));
            gsm[p] += (v0.x + v0.y) + (v0.z + v0.w) + (v1.x + v1.y) + (v1.z + v1.w);
            uint4 w;
            w.x = pack_bf16(v0.x, v0.y);
            w.y = pack_bf16(v0.z, v0.w);
            w.z = pack_bf16(v1.x, v1.y);
            w.w = pack_bf16(v1.z, v1.w);
            *(uint4*)&Bs0[row * S_ASTR + (bfo >> 1)] = w;
        }
    }
    __syncthreads();

    for (int nc = 0; nc < 512; nc += 32) {
        const int st = (nc >> 5) & 1;
        const uint32_t* Asb = ssm + st * S_STG;
        const uint32_t* Bsb = Asb + 64 * S_ASTR;
        const bool more = (nc + 32 < 512);

        uint4 a4;
        float4 v0[2], v1[2];
        if (more) {
            a4 = *(const uint4*)(kh + (size_t)arow * (Nn/2) + (nc + 32)/2 + aw4);
            #pragma unroll
            for (int p = 0; p < 2; p++) {
                int row = brow0 + p * 64;
                v0[p] = *(const float4*)(xp + (size_t)row * Nn + nc + 32 + bfo);
                v1[p] = *(const float4*)(xp + (size_t)row * Nn + nc + 32 + bfo + 4);
            }
        }

        #pragma unroll
        for (int s16 = 0; s16 < 2; s16++) {
            const int kb2 = s16 * 8;
            uint32_t afr[2][4];
            #pragma unroll
            for (int mi = 0; mi < 2; mi++) {
                int mr = wm * 32 + mi * 16;
                afr[mi][0] = Asb[(mr + g4    ) * S_ASTR + kb2 + l4];
                afr[mi][1] = Asb[(mr + g4 + 8) * S_ASTR + kb2 + l4];
                afr[mi][2] = Asb[(mr + g4    ) * S_ASTR + kb2 + l4 + 4];
                afr[mi][3] = Asb[(mr + g4 + 8) * S_ASTR + kb2 + l4 + 4];
            }
            uint32_t bfr[4][2];
            #pragma unroll
            for (int ni = 0; ni < 4; ni++) {
                int nr = wn * 32 + ni * 8 + g4;
                bfr[ni][0] = Bsb[nr * S_ASTR + kb2 + l4];
                bfr[ni][1] = Bsb[nr * S_ASTR + kb2 + l4 + 4];
            }
            #pragma unroll
            for (int mi = 0; mi < 2; mi++)
                #pragma unroll
                for (int ni = 0; ni < 4; ni++)
                    mma_bf16(acc[mi][ni], afr[mi], bfr[ni]);
        }

        if (more) {
            uint32_t* Asn = ssm + (1 - st) * S_STG;
            uint32_t* Bsn = Asn + 64 * S_ASTR;
            *(uint4*)&Asn[arow * S_ASTR + aw4] = a4;
            if (do_ks) {
                ksum += bf16_lo(a4.x) + bf16_hi(a4.x) + bf16_lo(a4.y) + bf16_hi(a4.y)
                      + bf16_lo(a4.z) + bf16_hi(a4.z) + bf16_lo(a4.w) + bf16_hi(a4.w);
            }
            #pragma unroll
            for (int p = 0; p < 2; p++) {
                int row = brow0 + p * 64;
                gmx[p] = fmaxf(gmx[p], fmaxf(fmaxf(fmaxf(v0[p].x, v0[p].y), fmaxf(v0[p].z, v0[p].w)),
                                             fmaxf(fmaxf(v1[p].x, v1[p].y), fmaxf(v1[p].z, v1[p].w))));
                gsm[p] += (v0[p].x + v0[p].y) + (v0[p].z + v0[p].w)
                        + (v1[p].x + v1[p].y) + (v1[p].z + v1[p].w);
                uint4 w;
                w.x = pack_bf16(v0[p].x, v0[p].y);
                w.y = pack_bf16(v0[p].z, v0[p].w);
                w.z = pack_bf16(v1[p].x, v1[p].y);
                w.w = pack_bf16(v1[p].z, v1[p].w);
                *(uint4*)&Bsn[row * S_ASTR + (bfo >> 1)] = w;
            }
        }
        __syncthreads();
    }

    if (do_ks) {
        ksum += __shfl_xor_sync(0xffffffffu, ksum, 1);
        ksum += __shfl_xor_sync(0xffffffffu, ksum, 2);
        if ((tid & 3) == 0) atomicAdd(&g_Ks2[b*Mm + arow], ksum);
    }

    #pragma unroll
    for (int p = 0; p < 2; p++) {
        float mx = gmx[p], sm = gsm[p];
        mx = fmaxf(mx, __shfl_xor_sync(0xffffffffu, mx, 1));
        sm += __shfl_xor_sync(0xffffffffu, sm, 1);
        mx = fmaxf(mx, __shfl_xor_sync(0xffffffffu, mx, 2));
        sm += __shfl_xor_sync(0xffffffffu, sm, 2);
        if ((tid & 3) == 0) {
            int c = c0 + brow0 + p * 64;
            atomicMaxF(&g_gmax[b*Cc + c], mx);
            atomicAdd(&g_gsum[b*Cc + c], sm);
        }
    }

    #pragma unroll
    for (int mi = 0; mi < 2; mi++) {
        #pragma unroll
        for (int h = 0; h < 2; h++) {
            const int m = wm * 32 + mi * 16 + h * 8 + g4;
            float* srow = g_S + (size_t)(b*Mm + m) * Cc + c0;
            #pragma unroll
            for (int ni = 0; ni < 4; ni++) {
                int c = wn * 32 + ni * 8 + l4 * 2;
                atomicAdd(srow + c,     acc[mi][ni][h*2 + 0]);
                atomicAdd(srow + c + 1, acc[mi][ni][h*2 + 1]);
            }
        }
    }
}

// ---------------- kernel: KVraw += S . Wv^T  (split-k x4, prefetched) ----------------
__global__ __launch_bounds__(256, 2) void kv2_kernel(const float* __restrict__ wv) {
    __shared__ float As[64][36];
    __shared__ float Bs[64][36];

    const int tid = threadIdx.x;
    const int wid = tid >> 5;
    const int lid = tid & 31;
    const int g4  = lid >> 2;
    const int l4  = lid & 3;
    const int wm  = wid >> 2;
    const int wn  = wid & 3;

    const int c0 = blockIdx.x * 64;
    const int kh = blockIdx.y * 128;
    const int b  = blockIdx.z;

    const float* sp  = g_S + (size_t)b * Mm * Cc + kh;
    const float* wvp = wv + (size_t)c0 * Cc + kh;

    float acc[2][2][4];
    #pragma unroll
    for (int mi = 0; mi < 2; mi++)
        #pragma unroll
        for (int ni = 0; ni < 2; ni++)
            #pragma unroll
            for (int q = 0; q < 4; q++) acc[mi][ni][q] = 0.f;

    const int lrow = tid >> 3;
    const int lf   = (tid & 7) * 4;

    float4 pa[2], pb[2];
    #pragma unroll
    for (int p = 0; p < 2; p++) {
        pa[p] = *(const float4*)(sp  + (size_t)(lrow + p*32) * Cc + lf);
        pb[p] = *(const float4*)(wvp + (size_t)(lrow + p*32) * Cc + lf);
    }

    for (int kc = 0; kc < 128; kc += 32) {
        if (kc) __syncthreads();
        #pragma unroll
        for (int p = 0; p < 2; p++) {
            int row = lrow + p * 32;
            *(float4*)&As[row][lf] = pa[p];
            *(float4*)&Bs[row][lf] = pb[p];
        }
        __syncthreads();
        if (kc + 32 < 128) {
            #pragma unroll
            for (int p = 0; p < 2; p++) {
                pa[p] = *(const float4*)(sp  + (size_t)(lrow + p*32) * Cc + kc + 32 + lf);
                pb[p] = *(const float4*)(wvp + (size_t)(lrow + p*32) * Cc + kc + 32 + lf);
            }
        }
        #pragma unroll
        for (int k8 = 0; k8 < 4; k8++) {
            const int kb = k8 * 8;
            uint32_t afr[2][4];
            #pragma unroll
            for (int mi = 0; mi < 2; mi++) {
                int mr = wm * 32 + mi * 16;
                afr[mi][0] = __float_as_uint(As[mr + g4    ][kb + l4]);
                afr[mi][1] = __float_as_uint(As[mr + g4 + 8][kb + l4]);
                afr[mi][2] = __float_as_uint(As[mr + g4    ][kb + l4 + 4]);
                afr[mi][3] = __float_as_uint(As[mr + g4 + 8][kb + l4 + 4]);
            }
            uint32_t bfr[2][2];
            #pragma unroll
            for (int ni = 0; ni < 2; ni++) {
                int nr = wn * 16 + ni * 8 + g4;
                bfr[ni][0] = __float_as_uint(Bs[nr][kb + l4]);
                bfr[ni][1] = __float_as_uint(Bs[nr][kb + l4 + 4]);
            }
            #pragma unroll
            for (int mi = 0; mi < 2; mi++)
                #pragma unroll
                for (int ni = 0; ni < 2; ni++)
                    mma_tf32(acc[mi][ni], afr[mi], bfr[ni]);
        }
    }

    #pragma unroll
    for (int mi = 0; mi < 2; mi++) {
        #pragma unroll
        for (int h = 0; h < 2; h++) {
            const int m = wm * 32 + mi * 16 + h * 8 + g4;
            float* kvrow = g_KV + (size_t)(b*Mm + m) * Cc;
            #pragma unroll
            for (int ni = 0; ni < 2; ni++) {
                int c = c0 + wn * 16 + ni * 8 + l4 * 2;
                atomicAdd(kvrow + c,     acc[mi][ni][h*2 + 0]);
                atomicAdd(kvrow + c + 1, acc[mi][ni][h*2 + 1]);
            }
        }
    }
}

// ---------------- kernel: out = x + gamma * norm * (KV^T @ Qf)  [bf16 m16n8k16] ----------------
// Qp  [32 m-pairs][132] : word = (Qf[2j][n], Qf[2j+1][n])
// KVp [32 m-pairs][264] : word = (KV[2j][c], KV[2j+1][c]) after gate/bv epilogue
#define OQ_STR  132
#define OKV_STR 264
#define OUT_SMEM ((32*OQ_STR + 32*OKV_STR + 64 + 128) * 4)
__global__ __launch_bounds__(512) void out_mma_kernel(const float* __restrict__ x,
                                                      const float* __restrict__ gamma,
                                                      const float* __restrict__ bv,
                                                      float* __restrict__ out) {
    extern __shared__ uint32_t osm[];
    uint32_t* Qp  = osm;                               // [32][132]
    uint32_t* KVp = osm + 32 * OQ_STR;                 // [32][264]
    float* ks_s   = (float*)(osm + 32*OQ_STR + 32*OKV_STR);   // [64]
    float* nrm_s  = ks_s + 64;                                 // [128]

    const int tid = threadIdx.x;
    const int wid = tid >> 5;
    const int lid = tid & 31;
    const int g4  = lid >> 2;
    const int l4  = lid & 3;
    const int wm  = wid >> 2;          // 0..3  (c, 64 each)
    const int wn  = wid & 3;           // 0..3  (n, 32 each)

    const int n0 = blockIdx.x * 128;
    const int c0 = blockIdx.y * 256;
    const int b  = blockIdx.z;

    const uint32_t* qb = g_Qh + (size_t)b * Mm * (Nn/2) + n0/2;
    const float* kvb = g_KV + (size_t)b * Mm * Cc;

    // Q load: repack n-packed bf16 into m-pair-packed. task: j = m-pair, w4 = n-word quad.
    {
        int j  = tid >> 4;             // 0..31
        int w4 = (tid & 15) * 4;       // 0..60
        const uint32_t* q0 = qb + (size_t)(2*j    ) * (Nn/2) + w4;
        const uint32_t* q1 = qb + (size_t)(2*j + 1) * (Nn/2) + w4;
        uint4 a = *(const uint4*)q0;
        uint4 c = *(const uint4*)q1;
        uint4 o0, o1;
        o0.x = __byte_perm(a.x, c.x, 0x5410);
        o0.y = __byte_perm(a.x, c.x, 0x7632);
        o0.z = __byte_perm(a.y, c.y, 0x5410);
        o0.w = __byte_perm(a.y, c.y, 0x7632);
        o1.x = __byte_perm(a.z, c.z, 0x5410);
        o1.y = __byte_perm(a.z, c.z, 0x7632);
        o1.z = __byte_perm(a.w, c.w, 0x5410);
        o1.w = __byte_perm(a.w, c.w, 0x7632);
        *(uint4*)&Qp[j * OQ_STR + w4 * 2]     = o0;
        *(uint4*)&Qp[j * OQ_STR + w4 * 2 + 4] = o1;
    }
    // KV load + epilogue + pack m-pairs. task: j = m-pair (idx>>6), c4 = (idx&63)*4.
    #pragma unroll
    for (int p = 0; p < 4; p++) {
        int idx = tid + p * 512;
        int j   = idx >> 6;
        int c4  = (idx & 63) * 4;
        const int cg = c0 + c4;
        float4 kv0 = *(const float4*)(kvb + (size_t)(2*j    ) * Cc + cg);
        float4 kv1 = *(const float4*)(kvb + (size_t)(2*j + 1) * Cc + cg);
        float ks0 = g_Ks2[b*Mm + 2*j];
        float ks1 = g_Ks2[b*Mm + 2*j + 1];
        float4 bvv = *(const float4*)(bv + cg);
        float4 gm = *(const float4*)(g_gmax + b*Cc + cg);
        float4 gs = *(const float4*)(g_gsum + b*Cc + cg);
        float gt0 = gm.x + gs.x * (1.f/Nn);
        float gt1 = gm.y + gs.y * (1.f/Nn);
        float gt2 = gm.z + gs.z * (1.f/Nn);
        float gt3 = gm.w + gs.w * (1.f/Nn);
        uint4 w;
        w.x = pack_bf16(gt0 * (kv0.x + ks0 * bvv.x), gt0 * (kv1.x + ks1 * bvv.x));
        w.y = pack_bf16(gt1 * (kv0.y + ks0 * bvv.y), gt1 * (kv1.y + ks1 * bvv.y));
        w.z = pack_bf16(gt2 * (kv0.z + ks0 * bvv.z), gt2 * (kv1.z + ks1 * bvv.z));
        w.w = pack_bf16(gt3 * (kv0.w + ks0 * bvv.w), gt3 * (kv1.w + ks1 * bvv.w));
        *(uint4*)&KVp[j * OKV_STR + c4] = w;
    }
    if (tid < 64) ks_s[tid] = g_Ks2[b*Mm + tid] + EPSc;
    __syncthreads();

    // in-block norm from packed Qp
    if (tid < 128) {
        float s = 0.f;
        #pragma unroll
        for (int j = 0; j < 32; j++) {
            uint32_t w = Qp[j * OQ_STR + tid];
            s = fmaf(bf16_lo(w), ks_s[2*j],     s);
            s = fmaf(bf16_hi(w), ks_s[2*j + 1], s);
        }
        nrm_s[tid] = 1.f / s;
    }
    __syncthreads();

    float acc[4][4][4];
    #pragma unroll
    for (int mi = 0; mi < 4; mi++)
        #pragma unroll
        for (int ni = 0; ni < 4; ni++)
            #pragma unroll
            for (int q = 0; q < 4; q++) acc[mi][ni][q] = 0.f;

    #pragma unroll
    for (int k16 = 0; k16 < 4; k16++) {
        const int kb2 = k16 * 8;
        uint32_t afr[4][4];
        #pragma unroll
        for (int mi = 0; mi < 4; mi++) {
            int cr = wm * 64 + mi * 16;
            afr[mi][0] = KVp[(kb2 + l4    ) * OKV_STR + cr + g4];
            afr[mi][1] = KVp[(kb2 + l4    ) * OKV_STR + cr + g4 + 8];
            afr[mi][2] = KVp[(kb2 + l4 + 4) * OKV_STR + cr + g4];
            afr[mi][3] = KVp[(kb2 + l4 + 4) * OKV_STR + cr + g4 + 8];
        }
        uint32_t bfr[4][2];
        #pragma unroll
        for (int ni = 0; ni < 4; ni++) {
            int nr = wn * 32 + ni * 8 + g4;
            bfr[ni][0] = Qp[(kb2 + l4    ) * OQ_STR + nr];
            bfr[ni][1] = Qp[(kb2 + l4 + 4) * OQ_STR + nr];
        }
        #pragma unroll
        for (int mi = 0; mi < 4; mi++)
            #pragma unroll
            for (int ni = 0; ni < 4; ni++)
                mma_bf16(acc[mi][ni], afr[mi], bfr[ni]);
    }

    const float g = gamma[0];
    float2 nrm[4];
    #pragma unroll
    for (int ni = 0; ni < 4; ni++)
        nrm[ni] = *(float2*)&nrm_s[wn*32 + ni*8 + l4*2];

    #pragma unroll
    for (int mi = 0; mi < 4; mi++) {
        #pragma unroll
        for (int h = 0; h < 2; h++) {
            const int c = c0 + wm * 64 + mi * 16 + h * 8 + g4;
            const size_t off = ((size_t)(b * Cc + c)) * Nn + n0;
            #pragma unroll
            for (int ni = 0; ni < 4; ni++) {
                int ncol = wn * 32 + ni * 8 + l4 * 2;
                float2 xv = *(const float2*)(x + off + ncol);
                float2 r;
                r.x = xv.x + g * nrm[ni].x * acc[mi][ni][h*2 + 0];
                r.y = xv.y + g * nrm[ni].y * acc[mi][ni][h*2 + 1];
                *(float2*)(out + off + ncol) = r;
            }
        }
    }
}

// ---------------- launch (single stream, 4 kernels) ----------------
extern "C" void kernel_launch(void* const* d_in, const int* in_sizes, int n_in,
                              void* d_out, int out_size) {
    const float* x     = (const float*)d_in[0];
    const float* wq    = (const float*)d_in[1];
    const float* bq    = (const float*)d_in[2];
    const float* wk    = (const float*)d_in[3];
    const float* bk    = (const float*)d_in[4];
    const float* wv    = (const float*)d_in[5];
    const float* bv    = (const float*)d_in[6];
    const float* gamma = (const float*)d_in[7];
    float* out = (float*)d_out;

    cudaFuncSetAttribute(qk_mma_kernel, cudaFuncAttributeMaxDynamicSharedMemorySize, QK_SMEM);
    cudaFuncSetAttribute(s_mma_kernel, cudaFuncAttributeMaxDynamicSharedMemorySize, S_SMEM);
    cudaFuncSetAttribute(out_mma_kernel, cudaFuncAttributeMaxDynamicSharedMemorySize, OUT_SMEM);

    qk_mma_kernel<<<dim3(Nn/128, Bz), 256, QK_SMEM>>>(x, wq, bq, wk, bk);
    s_mma_kernel<<<dim3(8, Cc/128, Bz), 256, S_SMEM>>>(x);
    kv2_kernel<<<dim3(Cc/64, 4, Bz), 256>>>(wv);
    out_mma_kernel<<<dim3(Nn/128, Cc/256, Bz), 512, OUT_SMEM>>>(x, gamma, bv, out);
}